// round 9
// baseline (speedup 1.0000x reference)
#include <cuda_runtime.h>
#include <cuda_bf16.h>
#include <cstdint>

#define SEQ 2048
#define DIM 1024
#define NHEAD 16
#define DHEAD 64
#define QKV_N (3 * DIM)   // 3072
#define NTILES (SEQ / 64) // 32

// ---------------------------------------------------------------------------
// Scratch (device globals — allocation-free rule)
// ---------------------------------------------------------------------------
__device__ __nv_bfloat16 g_x_hi[SEQ * DIM];
__device__ __nv_bfloat16 g_x_lo[SEQ * DIM];
__device__ __nv_bfloat16 g_wqkv_hi[QKV_N * DIM];   // [N,K] transposed
__device__ __nv_bfloat16 g_wqkv_lo[QKV_N * DIM];
__device__ __nv_bfloat16 g_wout_hi[DIM * DIM];     // [N,K] transposed
__device__ __nv_bfloat16 g_wout_lo[DIM * DIM];
__device__ __nv_bfloat16 g_qkv_hi[SEQ * QKV_N];
__device__ __nv_bfloat16 g_qkv_lo[SEQ * QKV_N];
__device__ __nv_bfloat16 g_attn_hi[SEQ * DIM];
__device__ __nv_bfloat16 g_attn_lo[SEQ * DIM];

// ---------------------------------------------------------------------------
// PTX helpers
// ---------------------------------------------------------------------------
__device__ __forceinline__ uint32_t smem_u32(const void* p) {
    uint32_t a;
    asm("{ .reg .u64 t; cvta.to.shared.u64 t, %1; cvt.u32.u64 %0, t; }"
        : "=r"(a) : "l"(p));
    return a;
}

__device__ __forceinline__ void ldsm_x4(uint32_t* r, uint32_t addr) {
    asm volatile("ldmatrix.sync.aligned.m8n8.x4.shared.b16 {%0,%1,%2,%3}, [%4];"
                 : "=r"(r[0]), "=r"(r[1]), "=r"(r[2]), "=r"(r[3]) : "r"(addr));
}

__device__ __forceinline__ void ldsm_x4_t(uint32_t* r, uint32_t addr) {
    asm volatile("ldmatrix.sync.aligned.m8n8.x4.trans.shared.b16 {%0,%1,%2,%3}, [%4];"
                 : "=r"(r[0]), "=r"(r[1]), "=r"(r[2]), "=r"(r[3]) : "r"(addr));
}

__device__ __forceinline__ void mma_bf16(float* d, const uint32_t* a,
                                         const uint32_t* b) {
    asm("mma.sync.aligned.m16n8k16.row.col.f32.bf16.bf16.f32 "
        "{%0,%1,%2,%3}, {%4,%5,%6,%7}, {%8,%9}, {%0,%1,%2,%3};"
        : "+f"(d[0]), "+f"(d[1]), "+f"(d[2]), "+f"(d[3])
        : "r"(a[0]), "r"(a[1]), "r"(a[2]), "r"(a[3]), "r"(b[0]), "r"(b[1]));
}

__device__ __forceinline__ void cp16(uint32_t dst, const void* src) {
    asm volatile("cp.async.cg.shared.global [%0], [%1], 16;"
                 :: "r"(dst), "l"(src));
}
#define CP_COMMIT()   asm volatile("cp.async.commit_group;" ::: "memory")
#define CP_WAIT_1()   asm volatile("cp.async.wait_group 1;" ::: "memory")
#define CP_WAIT_ALL() asm volatile("cp.async.wait_all;" ::: "memory")

// swizzled smem byte offset for (row, 16B-seg), 128B rows (8 segs)
#define SWZ(r, seg) ((uint32_t)((r) * 128 + (((seg) ^ ((r) & 7)) << 4)))
// swizzled smem byte offset for (row, 16B-seg), 64B rows (4 segs)
#define SWZ32(r, seg) ((uint32_t)((r) * 64 + (((seg) ^ (((r) >> 1) & 3)) << 4)))

// pack 2 floats into bf16x2 hi + residual bf16x2 lo
__device__ __forceinline__ void split_pack(float x, float y,
                                           uint32_t& hi, uint32_t& lo) {
    __nv_bfloat162 h = __floats2bfloat162_rn(x, y);
    float2 hf = __bfloat1622float2(h);
    __nv_bfloat162 l = __floats2bfloat162_rn(x - hf.x, y - hf.y);
    hi = *reinterpret_cast<uint32_t*>(&h);
    lo = *reinterpret_cast<uint32_t*>(&l);
}

// ---------------------------------------------------------------------------
// Elementwise split: fp32 -> bf16 hi + bf16 lo
// ---------------------------------------------------------------------------
__global__ __launch_bounds__(256) void split_kernel(
    const float* __restrict__ in,
    __nv_bfloat16* __restrict__ hi, __nv_bfloat16* __restrict__ lo)
{
    int i = (blockIdx.x * 256 + threadIdx.x) * 4;
    float4 v = *(const float4*)(in + i);
    uint32_t h0, l0, h1, l1;
    split_pack(v.x, v.y, h0, l0);
    split_pack(v.z, v.w, h1, l1);
    *(uint32_t*)(hi + i)     = h0;
    *(uint32_t*)(hi + i + 2) = h1;
    *(uint32_t*)(lo + i)     = l0;
    *(uint32_t*)(lo + i + 2) = l1;
}

// ---------------------------------------------------------------------------
// Transpose + split: W[K,N] fp32 -> Wt[N,K] bf16 hi/lo. 32x32 tiles.
// ---------------------------------------------------------------------------
__global__ __launch_bounds__(256) void tsplit_kernel(
    const float* __restrict__ W,
    __nv_bfloat16* __restrict__ hi, __nv_bfloat16* __restrict__ lo,
    int K, int N)
{
    __shared__ float t[32][33];
    const int n0 = blockIdx.x * 32, k0 = blockIdx.y * 32;
    const int tx = threadIdx.x, ty = threadIdx.y;   // 32 x 8

    #pragma unroll
    for (int j = 0; j < 4; j++)
        t[ty + 8 * j][tx] = W[(size_t)(k0 + ty + 8 * j) * N + n0 + tx];
    __syncthreads();

    #pragma unroll
    for (int j = 0; j < 4; j++) {
        int row = ty + 8 * j;
        float v = t[tx][row];
        __nv_bfloat16 h = __float2bfloat16(v);
        size_t o = (size_t)(n0 + row) * K + k0 + tx;
        hi[o] = h;
        lo[o] = __float2bfloat16(v - __bfloat162float(h));
    }
}

// ---------------------------------------------------------------------------
// Split-bf16 tensor-core GEMM via mma.sync (3 terms, fp32 accum).
// 64x128 CTA tile (small scheduling quantum -> good wave fill), BK=32,
// 2-stage cp.async pipeline. 8 warps as 2m x 4n, warp tile 32x32.
// Stage = Ahi(4K)+Alo(4K)+Bhi(8K)+Blo(8K) = 24KB; 2 stages = 48KB.
// ---------------------------------------------------------------------------
#define G_STAGE 24576
#define G_SMEM  (2 * G_STAGE)

__global__ __launch_bounds__(256, 2) void gemm_mma(
    const __nv_bfloat16* __restrict__ Ahi, const __nv_bfloat16* __restrict__ Alo,
    const __nv_bfloat16* __restrict__ Bhi, const __nv_bfloat16* __restrict__ Blo,
    float* __restrict__ C,
    __nv_bfloat16* __restrict__ Chi, __nv_bfloat16* __restrict__ Clo,
    int Mtot, int Ntot, int Ktot,
    const float* __restrict__ bias)
{
    extern __shared__ char smem[];
    const uint32_t sb = smem_u32(smem);
    const int tid  = threadIdx.x;
    const int wid  = tid >> 5;
    const int lane = tid & 31;
    const int row0 = blockIdx.y * 64, col0 = blockIdx.x * 128;

    const int m0 = (wid & 1) * 32;     // warp row offset (2 m-groups)
    const int n0 = (wid >> 1) * 32;    // warp col offset (4 n-groups)

    // stage layout: [0,4K) Ahi | [4K,8K) Alo | [8K,16K) Bhi | [16K,24K) Blo
    auto load_chunk = [&](int c, int stg) {
        const uint32_t base = sb + stg * G_STAGE;
        #pragma unroll
        for (int i = 0; i < 6; i++) {
            if (i < 2) {
                // A hi/lo: 64 rows x 4 segs = 256 cp16
                int r = tid >> 2, seg = tid & 3;
                const __nv_bfloat16* src = (i == 0 ? Ahi : Alo)
                                         + (size_t)(row0 + r) * Ktot;
                cp16(base + i * 4096 + SWZ32(r, seg), src + c * 32 + seg * 8);
            } else {
                // B hi/lo: 128 rows x 4 segs = 512 cp16 each
                const int half = (i - 2) & 1;          // two passes per tile
                const int isLo = (i >= 4);
                int local = tid + half * 256;
                int r = local >> 2, seg = local & 3;
                const __nv_bfloat16* src = (isLo ? Blo : Bhi)
                                         + (size_t)(col0 + r) * Ktot;
                cp16(base + 8192 + isLo * 8192 + SWZ32(r, seg),
                     src + c * 32 + seg * 8);
            }
        }
    };

    float acc[2][4][4] = {};
    const int nchunks = Ktot >> 5;

    load_chunk(0, 0);
    CP_COMMIT();

    for (int c = 0; c < nchunks; c++) {
        if (c + 1 < nchunks) load_chunk(c + 1, (c + 1) & 1);
        CP_COMMIT();
        CP_WAIT_1();
        __syncthreads();

        const uint32_t st  = sb + (c & 1) * G_STAGE;
        const uint32_t sA  = st;
        const uint32_t sAL = st + 4096;
        const uint32_t sB  = st + 8192;
        const uint32_t sBL = st + 16384;

        #pragma unroll
        for (int ks = 0; ks < 2; ks++) {
            uint32_t aH[2][4], aL[2][4];
            #pragma unroll
            for (int mt = 0; mt < 2; mt++) {
                int r   = m0 + mt * 16 + (lane & 15);
                int seg = ks * 2 + (lane >> 4);
                uint32_t off = SWZ32(r, seg);
                ldsm_x4(aH[mt], sA  + off);
                ldsm_x4(aL[mt], sAL + off);
            }
            #pragma unroll
            for (int np = 0; np < 2; np++) {
                int nr  = n0 + np * 16 + ((lane >> 4) << 3) + (lane & 7);
                int seg = ks * 2 + ((lane >> 3) & 1);
                uint32_t off = SWZ32(nr, seg);
                uint32_t bH[4], bL[4];
                ldsm_x4(bH, sB  + off);
                ldsm_x4(bL, sBL + off);
                #pragma unroll
                for (int mt = 0; mt < 2; mt++) {
                    mma_bf16(acc[mt][np * 2],     aH[mt], bH);
                    mma_bf16(acc[mt][np * 2 + 1], aH[mt], bH + 2);
                    mma_bf16(acc[mt][np * 2],     aH[mt], bL);
                    mma_bf16(acc[mt][np * 2 + 1], aH[mt], bL + 2);
                    mma_bf16(acc[mt][np * 2],     aL[mt], bH);
                    mma_bf16(acc[mt][np * 2 + 1], aL[mt], bH + 2);
                }
            }
        }
        __syncthreads();
    }

    #pragma unroll
    for (int mt = 0; mt < 2; mt++) {
        int r = row0 + m0 + mt * 16 + (lane >> 2);
        #pragma unroll
        for (int nt = 0; nt < 4; nt++) {
            int cc = col0 + n0 + nt * 8 + (lane & 3) * 2;
            float bx = 0.f, by = 0.f;
            if (bias) { bx = bias[cc]; by = bias[cc + 1]; }
            float v0x = acc[mt][nt][0] + bx, v0y = acc[mt][nt][1] + by;
            float v1x = acc[mt][nt][2] + bx, v1y = acc[mt][nt][3] + by;
            if (Chi) {
                uint32_t h0, l0, h1, l1;
                split_pack(v0x, v0y, h0, l0);
                split_pack(v1x, v1y, h1, l1);
                *(uint32_t*)&Chi[(size_t)r * Ntot + cc]       = h0;
                *(uint32_t*)&Clo[(size_t)r * Ntot + cc]       = l0;
                *(uint32_t*)&Chi[(size_t)(r + 8) * Ntot + cc] = h1;
                *(uint32_t*)&Clo[(size_t)(r + 8) * Ntot + cc] = l1;
            } else {
                *(float2*)&C[(size_t)r * Ntot + cc]       = make_float2(v0x, v0y);
                *(float2*)&C[(size_t)(r + 8) * Ntot + cc] = make_float2(v1x, v1y);
            }
        }
    }
}

// ---------------------------------------------------------------------------
// Paired-tile flash attention (causal load balancing) — unchanged from R8.
// ---------------------------------------------------------------------------
#define AT_SMEM 65536

__global__ __launch_bounds__(128, 2) void attn_mma(
    const __nv_bfloat16* __restrict__ qkv_hi,
    const __nv_bfloat16* __restrict__ qkv_lo,
    __nv_bfloat16* __restrict__ out_hi,
    __nv_bfloat16* __restrict__ out_lo)
{
    extern __shared__ char smem[];
    const uint32_t sb = smem_u32(smem);
    const uint32_t sQ1h = sb,         sQ1l = sb + 8192;
    const uint32_t sQ2h = sb + 16384, sQ2l = sb + 24576;
    const uint32_t sKh  = sb + 32768, sKl  = sb + 40960;
    const uint32_t sVh  = sb + 49152, sVl  = sb + 57344;

    const int tid = threadIdx.x, wid = tid >> 5, lane = tid & 31;
    const int t1 = blockIdx.x;
    const int t2 = (NTILES - 1) - t1;
    const int h  = blockIdx.y;
    const int hoff = h * DHEAD;

    #pragma unroll
    for (int i = 0; i < 4; i++) {
        int idx = tid + i * 128;
        int r = idx >> 3, seg = idx & 7;
        uint32_t off = SWZ(r, seg);
        size_t g1 = (size_t)(t1 * 64 + r) * QKV_N + hoff + seg * 8;
        size_t g2 = (size_t)(t2 * 64 + r) * QKV_N + hoff + seg * 8;
        cp16(sQ1h + off, qkv_hi + g1);
        cp16(sQ1l + off, qkv_lo + g1);
        cp16(sQ2h + off, qkv_hi + g2);
        cp16(sQ2l + off, qkv_lo + g2);
    }

    float o1[8][4] = {}, o2[8][4] = {};
    float m1[2] = {-1e30f, -1e30f}, l1[2] = {0.f, 0.f};
    float m2[2] = {-1e30f, -1e30f}, l2[2] = {0.f, 0.f};

    const int rloc = wid * 16 + (lane >> 2);
    const int rA1 = t1 * 64 + rloc;
    const int rA2 = t2 * 64 + rloc;

    auto process = [&](uint32_t sQh, uint32_t sQl, float (*o)[4],
                       float* m_i, float* l_i, int rA, bool maskit, int k0) {
        float s[8][4] = {};
        #pragma unroll
        for (int ks = 0; ks < 4; ks++) {
            uint32_t aH[4], aL[4];
            {
                int r   = wid * 16 + (lane & 15);
                int seg = ks * 2 + (lane >> 4);
                ldsm_x4(aH, sQh + SWZ(r, seg));
                ldsm_x4(aL, sQl + SWZ(r, seg));
            }
            #pragma unroll
            for (int np = 0; np < 4; np++) {
                int nr = np * 16 + ((lane >> 4) << 3) + (lane & 7);
                int sg = ks * 2 + ((lane >> 3) & 1);
                uint32_t off = SWZ(nr, sg);
                uint32_t bH[4], bL[4];
                ldsm_x4(bH, sKh + off);
                ldsm_x4(bL, sKl + off);
                mma_bf16(s[np * 2],     aH, bH);
                mma_bf16(s[np * 2 + 1], aH, bH + 2);
                mma_bf16(s[np * 2],     aH, bL);
                mma_bf16(s[np * 2 + 1], aH, bL + 2);
                mma_bf16(s[np * 2],     aL, bH);
                mma_bf16(s[np * 2 + 1], aL, bH + 2);
            }
        }

        #pragma unroll
        for (int j = 0; j < 8; j++) {
            s[j][0] *= 0.125f; s[j][1] *= 0.125f;
            s[j][2] *= 0.125f; s[j][3] *= 0.125f;
        }
        if (maskit) {
            #pragma unroll
            for (int j = 0; j < 8; j++) {
                int col = k0 + j * 8 + (lane & 3) * 2;
                if (col > rA)         s[j][0] = -1e30f;
                if (col + 1 > rA)     s[j][1] = -1e30f;
                if (col > rA + 8)     s[j][2] = -1e30f;
                if (col + 1 > rA + 8) s[j][3] = -1e30f;
            }
        }

        float mxA = -1e30f, mxB = -1e30f;
        #pragma unroll
        for (int j = 0; j < 8; j++) {
            mxA = fmaxf(mxA, fmaxf(s[j][0], s[j][1]));
            mxB = fmaxf(mxB, fmaxf(s[j][2], s[j][3]));
        }
        mxA = fmaxf(mxA, __shfl_xor_sync(0xffffffffu, mxA, 1));
        mxA = fmaxf(mxA, __shfl_xor_sync(0xffffffffu, mxA, 2));
        mxB = fmaxf(mxB, __shfl_xor_sync(0xffffffffu, mxB, 1));
        mxB = fmaxf(mxB, __shfl_xor_sync(0xffffffffu, mxB, 2));

        float mA = fmaxf(m_i[0], mxA), mB = fmaxf(m_i[1], mxB);
        float scA = __expf(m_i[0] - mA), scB = __expf(m_i[1] - mB);
        float lA = 0.f, lB = 0.f;
        #pragma unroll
        for (int j = 0; j < 8; j++) {
            s[j][0] = __expf(s[j][0] - mA);
            s[j][1] = __expf(s[j][1] - mA);
            s[j][2] = __expf(s[j][2] - mB);
            s[j][3] = __expf(s[j][3] - mB);
            lA += s[j][0] + s[j][1];
            lB += s[j][2] + s[j][3];
        }
        lA += __shfl_xor_sync(0xffffffffu, lA, 1);
        lA += __shfl_xor_sync(0xffffffffu, lA, 2);
        lB += __shfl_xor_sync(0xffffffffu, lB, 1);
        lB += __shfl_xor_sync(0xffffffffu, lB, 2);
        l_i[0] = l_i[0] * scA + lA;  m_i[0] = mA;
        l_i[1] = l_i[1] * scB + lB;  m_i[1] = mB;
        #pragma unroll
        for (int j = 0; j < 8; j++) {
            o[j][0] *= scA; o[j][1] *= scA;
            o[j][2] *= scB; o[j][3] *= scB;
        }

        #pragma unroll
        for (int t = 0; t < 4; t++) {
            uint32_t pH[4], pL[4];
            split_pack(s[2 * t][0],     s[2 * t][1],     pH[0], pL[0]);
            split_pack(s[2 * t][2],     s[2 * t][3],     pH[1], pL[1]);
            split_pack(s[2 * t + 1][0], s[2 * t + 1][1], pH[2], pL[2]);
            split_pack(s[2 * t + 1][2], s[2 * t + 1][3], pH[3], pL[3]);
            #pragma unroll
            for (int sp = 0; sp < 4; sp++) {
                int g  = lane >> 3, rr = lane & 7;
                uint32_t off = SWZ(t * 16 + rr + ((g & 1) << 3),
                                   sp * 2 + (g >> 1));
                uint32_t bH[4], bL[4];
                ldsm_x4_t(bH, sVh + off);
                ldsm_x4_t(bL, sVl + off);
                mma_bf16(o[sp * 2],     pH, bH);
                mma_bf16(o[sp * 2 + 1], pH, bH + 2);
                mma_bf16(o[sp * 2],     pH, bL);
                mma_bf16(o[sp * 2 + 1], pH, bL + 2);
                mma_bf16(o[sp * 2],     pL, bH);
                mma_bf16(o[sp * 2 + 1], pL, bH + 2);
            }
        }
    };

    for (int kt = 0; kt <= t2; kt++) {
        const int k0 = kt * 64;

        #pragma unroll
        for (int i = 0; i < 4; i++) {
            int idx = tid + i * 128;
            int r = idx >> 3, seg = idx & 7;
            size_t g = (size_t)(k0 + r) * QKV_N + DIM + hoff + seg * 8;
            uint32_t off = SWZ(r, seg);
            cp16(sKh + off, qkv_hi + g);
            cp16(sKl + off, qkv_lo + g);
            cp16(sVh + off, qkv_hi + g + DIM);
            cp16(sVl + off, qkv_lo + g + DIM);
        }
        CP_WAIT_ALL();
        __syncthreads();

        process(sQ2h, sQ2l, o2, m2, l2, rA2, kt == t2, k0);
        if (kt <= t1)
            process(sQ1h, sQ1l, o1, m1, l1, rA1, kt == t1, k0);

        __syncthreads();
    }

    {
        float invA = 1.0f / l2[0], invB = 1.0f / l2[1];
        #pragma unroll
        for (int j = 0; j < 8; j++) {
            int d = hoff + j * 8 + (lane & 3) * 2;
            uint32_t hA, lA2, hB, lB2;
            split_pack(o2[j][0] * invA, o2[j][1] * invA, hA, lA2);
            split_pack(o2[j][2] * invB, o2[j][3] * invB, hB, lB2);
            *(uint32_t*)&out_hi[(size_t)rA2 * DIM + d]       = hA;
            *(uint32_t*)&out_lo[(size_t)rA2 * DIM + d]       = lA2;
            *(uint32_t*)&out_hi[(size_t)(rA2 + 8) * DIM + d] = hB;
            *(uint32_t*)&out_lo[(size_t)(rA2 + 8) * DIM + d] = lB2;
        }
    }
    {
        float invA = 1.0f / l1[0], invB = 1.0f / l1[1];
        #pragma unroll
        for (int j = 0; j < 8; j++) {
            int d = hoff + j * 8 + (lane & 3) * 2;
            uint32_t hA, lA2, hB, lB2;
            split_pack(o1[j][0] * invA, o1[j][1] * invA, hA, lA2);
            split_pack(o1[j][2] * invB, o1[j][3] * invB, hB, lB2);
            *(uint32_t*)&out_hi[(size_t)rA1 * DIM + d]       = hA;
            *(uint32_t*)&out_lo[(size_t)rA1 * DIM + d]       = lA2;
            *(uint32_t*)&out_hi[(size_t)(rA1 + 8) * DIM + d] = hB;
            *(uint32_t*)&out_lo[(size_t)(rA1 + 8) * DIM + d] = lB2;
        }
    }
}

// ---------------------------------------------------------------------------
extern "C" void kernel_launch(void* const* d_in, const int* in_sizes, int n_in,
                              void* d_out, int out_size)
{
    const float* x    = (const float*)d_in[0];
    const float* Wqkv = (const float*)d_in[1];
    const float* Wout = (const float*)d_in[2];
    const float* bias = (const float*)d_in[3];
    float* out = (float*)d_out;

    __nv_bfloat16 *xh, *xl, *wqh, *wql, *woh, *wol, *qh, *ql, *ah, *al;
    cudaGetSymbolAddress((void**)&xh,  g_x_hi);
    cudaGetSymbolAddress((void**)&xl,  g_x_lo);
    cudaGetSymbolAddress((void**)&wqh, g_wqkv_hi);
    cudaGetSymbolAddress((void**)&wql, g_wqkv_lo);
    cudaGetSymbolAddress((void**)&woh, g_wout_hi);
    cudaGetSymbolAddress((void**)&wol, g_wout_lo);
    cudaGetSymbolAddress((void**)&qh,  g_qkv_hi);
    cudaGetSymbolAddress((void**)&ql,  g_qkv_lo);
    cudaGetSymbolAddress((void**)&ah,  g_attn_hi);
    cudaGetSymbolAddress((void**)&al,  g_attn_lo);

    cudaFuncSetAttribute(gemm_mma, cudaFuncAttributeMaxDynamicSharedMemorySize,
                         G_SMEM);
    cudaFuncSetAttribute(attn_mma, cudaFuncAttributeMaxDynamicSharedMemorySize,
                         AT_SMEM);

    // Prep: split x, transpose+split weights
    split_kernel<<<SEQ * DIM / 1024, 256>>>(x, xh, xl);
    tsplit_kernel<<<dim3(QKV_N / 32, DIM / 32), dim3(32, 8)>>>(Wqkv, wqh, wql,
                                                               DIM, QKV_N);
    tsplit_kernel<<<dim3(DIM / 32, DIM / 32), dim3(32, 8)>>>(Wout, woh, wol,
                                                             DIM, DIM);

    // 1) qkv = x @ Wqkv  -> bf16 hi/lo directly  (grid 24 x 32 = 768 CTAs)
    gemm_mma<<<dim3(QKV_N / 128, SEQ / 64), 256, G_SMEM>>>(
        xh, xl, wqh, wql, nullptr, qh, ql, SEQ, QKV_N, DIM, nullptr);

    // 2) attention (paired tiles) -> bf16 hi/lo directly
    attn_mma<<<dim3(NTILES / 2, NHEAD), 128, AT_SMEM>>>(qh, ql, ah, al);

    // 3) out = attn @ Wout + bias  (grid 8 x 32 = 256 CTAs)
    gemm_mma<<<dim3(DIM / 128, SEQ / 64), 256, G_SMEM>>>(
        ah, al, woh, wol, out, nullptr, nullptr, SEQ, DIM, DIM, bias);
}

// round 10
// speedup vs baseline: 1.2545x; 1.2545x over previous
#include <cuda_runtime.h>
#include <cuda_bf16.h>
#include <cuda_fp16.h>
#include <cstdint>

#define SEQ 2048
#define DIM 1024
#define NHEAD 16
#define DHEAD 64
#define QKV_N (3 * DIM)   // 3072
#define NTILES (SEQ / 64) // 32

// ---------------------------------------------------------------------------
// Scratch (device globals — allocation-free rule)
// ---------------------------------------------------------------------------
__device__ __nv_bfloat16 g_x_hi[SEQ * DIM];
__device__ __nv_bfloat16 g_x_lo[SEQ * DIM];
__device__ __nv_bfloat16 g_wqkv_hi[QKV_N * DIM];   // [N,K] transposed
__device__ __nv_bfloat16 g_wqkv_lo[QKV_N * DIM];
__device__ __nv_bfloat16 g_qkv_hi[SEQ * QKV_N];
__device__ __nv_bfloat16 g_qkv_lo[SEQ * QKV_N];
__device__ __half        g_v_f16[SEQ * DIM];       // fp16 copy of V columns
__device__ __half        g_wout_f16[DIM * DIM];    // [N,K] transposed, fp16
__device__ __half        g_attn_f16[SEQ * DIM];    // attention output, fp16

// ---------------------------------------------------------------------------
// PTX helpers
// ---------------------------------------------------------------------------
__device__ __forceinline__ uint32_t smem_u32(const void* p) {
    uint32_t a;
    asm("{ .reg .u64 t; cvta.to.shared.u64 t, %1; cvt.u32.u64 %0, t; }"
        : "=r"(a) : "l"(p));
    return a;
}

__device__ __forceinline__ void ldsm_x4(uint32_t* r, uint32_t addr) {
    asm volatile("ldmatrix.sync.aligned.m8n8.x4.shared.b16 {%0,%1,%2,%3}, [%4];"
                 : "=r"(r[0]), "=r"(r[1]), "=r"(r[2]), "=r"(r[3]) : "r"(addr));
}

__device__ __forceinline__ void ldsm_x4_t(uint32_t* r, uint32_t addr) {
    asm volatile("ldmatrix.sync.aligned.m8n8.x4.trans.shared.b16 {%0,%1,%2,%3}, [%4];"
                 : "=r"(r[0]), "=r"(r[1]), "=r"(r[2]), "=r"(r[3]) : "r"(addr));
}

__device__ __forceinline__ void mma_bf16(float* d, const uint32_t* a,
                                         const uint32_t* b) {
    asm("mma.sync.aligned.m16n8k16.row.col.f32.bf16.bf16.f32 "
        "{%0,%1,%2,%3}, {%4,%5,%6,%7}, {%8,%9}, {%0,%1,%2,%3};"
        : "+f"(d[0]), "+f"(d[1]), "+f"(d[2]), "+f"(d[3])
        : "r"(a[0]), "r"(a[1]), "r"(a[2]), "r"(a[3]), "r"(b[0]), "r"(b[1]));
}

__device__ __forceinline__ void mma_f16(float* d, const uint32_t* a,
                                        const uint32_t* b) {
    asm("mma.sync.aligned.m16n8k16.row.col.f32.f16.f16.f32 "
        "{%0,%1,%2,%3}, {%4,%5,%6,%7}, {%8,%9}, {%0,%1,%2,%3};"
        : "+f"(d[0]), "+f"(d[1]), "+f"(d[2]), "+f"(d[3])
        : "r"(a[0]), "r"(a[1]), "r"(a[2]), "r"(a[3]), "r"(b[0]), "r"(b[1]));
}

__device__ __forceinline__ void cp16(uint32_t dst, const void* src) {
    asm volatile("cp.async.cg.shared.global [%0], [%1], 16;"
                 :: "r"(dst), "l"(src));
}
#define CP_WAIT_ALL() asm volatile("cp.async.wait_all;" ::: "memory")

// swizzled smem byte offset for (row, 16B-seg), 128B rows (8 segs)
#define SWZ(r, seg) ((uint32_t)((r) * 128 + (((seg) ^ ((r) & 7)) << 4)))

// pack 2 floats into bf16x2 hi + residual bf16x2 lo
__device__ __forceinline__ void split_pack(float x, float y,
                                           uint32_t& hi, uint32_t& lo) {
    __nv_bfloat162 h = __floats2bfloat162_rn(x, y);
    float2 hf = __bfloat1622float2(h);
    __nv_bfloat162 l = __floats2bfloat162_rn(x - hf.x, y - hf.y);
    hi = *reinterpret_cast<uint32_t*>(&h);
    lo = *reinterpret_cast<uint32_t*>(&l);
}

__device__ __forceinline__ uint32_t pack_f16(float x, float y) {
    __half2 h = __floats2half2_rn(x, y);
    return *reinterpret_cast<uint32_t*>(&h);
}

// ---------------------------------------------------------------------------
// Elementwise split: fp32 -> bf16 hi + bf16 lo
// ---------------------------------------------------------------------------
__global__ __launch_bounds__(256) void split_kernel(
    const float* __restrict__ in,
    __nv_bfloat16* __restrict__ hi, __nv_bfloat16* __restrict__ lo)
{
    int i = (blockIdx.x * 256 + threadIdx.x) * 4;
    float4 v = *(const float4*)(in + i);
    uint32_t h0, l0, h1, l1;
    split_pack(v.x, v.y, h0, l0);
    split_pack(v.z, v.w, h1, l1);
    *(uint32_t*)(hi + i)     = h0;
    *(uint32_t*)(hi + i + 2) = h1;
    *(uint32_t*)(lo + i)     = l0;
    *(uint32_t*)(lo + i + 2) = l1;
}

// ---------------------------------------------------------------------------
// Transpose + split (bf16 hi/lo): W[K,N] fp32 -> Wt[N,K]. 32x32 tiles.
// ---------------------------------------------------------------------------
__global__ __launch_bounds__(256) void tsplit_kernel(
    const float* __restrict__ W,
    __nv_bfloat16* __restrict__ hi, __nv_bfloat16* __restrict__ lo,
    int K, int N)
{
    __shared__ float t[32][33];
    const int n0 = blockIdx.x * 32, k0 = blockIdx.y * 32;
    const int tx = threadIdx.x, ty = threadIdx.y;   // 32 x 8

    #pragma unroll
    for (int j = 0; j < 4; j++)
        t[ty + 8 * j][tx] = W[(size_t)(k0 + ty + 8 * j) * N + n0 + tx];
    __syncthreads();

    #pragma unroll
    for (int j = 0; j < 4; j++) {
        int row = ty + 8 * j;
        float v = t[tx][row];
        __nv_bfloat16 h = __float2bfloat16(v);
        size_t o = (size_t)(n0 + row) * K + k0 + tx;
        hi[o] = h;
        lo[o] = __float2bfloat16(v - __bfloat162float(h));
    }
}

// ---------------------------------------------------------------------------
// Transpose + convert (fp16 single): W[K,N] fp32 -> Wt[N,K]. 32x32 tiles.
// ---------------------------------------------------------------------------
__global__ __launch_bounds__(256) void tconv_f16_kernel(
    const float* __restrict__ W, __half* __restrict__ out, int K, int N)
{
    __shared__ float t[32][33];
    const int n0 = blockIdx.x * 32, k0 = blockIdx.y * 32;
    const int tx = threadIdx.x, ty = threadIdx.y;

    #pragma unroll
    for (int j = 0; j < 4; j++)
        t[ty + 8 * j][tx] = W[(size_t)(k0 + ty + 8 * j) * N + n0 + tx];
    __syncthreads();

    #pragma unroll
    for (int j = 0; j < 4; j++) {
        int row = ty + 8 * j;
        out[(size_t)(n0 + row) * K + k0 + tx] = __float2half(t[tx][row]);
    }
}

// ---------------------------------------------------------------------------
// Split-bf16 tensor-core GEMM (3 terms, fp32 accum). R5-proven config:
// 128x128 tile, BK=64, single 64KB buffer, 8 warps 4m x 2n, 2 CTAs/SM.
// Outputs: bf16 hi/lo split (qkv) + fp16 copy of the V columns (cc >= 2*DIM).
// ---------------------------------------------------------------------------
#define G_SMEM (4 * 16384)

__global__ __launch_bounds__(256, 2) void gemm_mma(
    const __nv_bfloat16* __restrict__ Ahi, const __nv_bfloat16* __restrict__ Alo,
    const __nv_bfloat16* __restrict__ Bhi, const __nv_bfloat16* __restrict__ Blo,
    __nv_bfloat16* __restrict__ Chi, __nv_bfloat16* __restrict__ Clo,
    __half* __restrict__ Cv16,
    int Mtot, int Ntot, int Ktot)
{
    extern __shared__ char smem[];
    const uint32_t sb = smem_u32(smem);
    const int tid  = threadIdx.x;
    const int wid  = tid >> 5;
    const int lane = tid & 31;
    const int row0 = blockIdx.y * 128, col0 = blockIdx.x * 128;

    const int m0 = (wid & 3) * 32;
    const int n0 = (wid >> 2) * 64;

    const uint32_t sA  = sb;
    const uint32_t sAL = sb + 16384;
    const uint32_t sB  = sb + 32768;
    const uint32_t sBL = sb + 49152;

    float acc[2][8][4] = {};

    const int nchunks = Ktot >> 6;
    for (int c = 0; c < nchunks; c++) {
        #pragma unroll
        for (int i = 0; i < 16; i++) {
            const int tile = i >> 2;
            int idx = tid + i * 256;
            int r   = (idx >> 3) & 127;
            int seg = idx & 7;
            const __nv_bfloat16* src;
            if (tile == 0)      src = Ahi + (size_t)(row0 + r) * Ktot;
            else if (tile == 1) src = Alo + (size_t)(row0 + r) * Ktot;
            else if (tile == 2) src = Bhi + (size_t)(col0 + r) * Ktot;
            else                src = Blo + (size_t)(col0 + r) * Ktot;
            cp16(sb + tile * 16384 + SWZ(r, seg), src + c * 64 + seg * 8);
        }
        CP_WAIT_ALL();
        __syncthreads();

        #pragma unroll
        for (int ks = 0; ks < 4; ks++) {
            uint32_t aH[2][4], aL[2][4];
            #pragma unroll
            for (int mt = 0; mt < 2; mt++) {
                int r   = m0 + mt * 16 + (lane & 15);
                int seg = ks * 2 + (lane >> 4);
                uint32_t off = SWZ(r, seg);
                ldsm_x4(aH[mt], sA  + off);
                ldsm_x4(aL[mt], sAL + off);
            }
            #pragma unroll
            for (int np = 0; np < 4; np++) {
                int nr  = n0 + np * 16 + ((lane >> 4) << 3) + (lane & 7);
                int seg = ks * 2 + ((lane >> 3) & 1);
                uint32_t off = SWZ(nr, seg);
                uint32_t bH[4], bL[4];
                ldsm_x4(bH, sB  + off);
                ldsm_x4(bL, sBL + off);
                #pragma unroll
                for (int mt = 0; mt < 2; mt++) {
                    mma_bf16(acc[mt][np * 2],     aH[mt], bH);
                    mma_bf16(acc[mt][np * 2 + 1], aH[mt], bH + 2);
                    mma_bf16(acc[mt][np * 2],     aH[mt], bL);
                    mma_bf16(acc[mt][np * 2 + 1], aH[mt], bL + 2);
                    mma_bf16(acc[mt][np * 2],     aL[mt], bH);
                    mma_bf16(acc[mt][np * 2 + 1], aL[mt], bH + 2);
                }
            }
        }
        __syncthreads();
    }

    #pragma unroll
    for (int mt = 0; mt < 2; mt++) {
        int r = row0 + m0 + mt * 16 + (lane >> 2);
        #pragma unroll
        for (int nt = 0; nt < 8; nt++) {
            int cc = col0 + n0 + nt * 8 + (lane & 3) * 2;
            float v0x = acc[mt][nt][0], v0y = acc[mt][nt][1];
            float v1x = acc[mt][nt][2], v1y = acc[mt][nt][3];
            uint32_t h0, l0, h1, l1;
            split_pack(v0x, v0y, h0, l0);
            split_pack(v1x, v1y, h1, l1);
            *(uint32_t*)&Chi[(size_t)r * Ntot + cc]       = h0;
            *(uint32_t*)&Clo[(size_t)r * Ntot + cc]       = l0;
            *(uint32_t*)&Chi[(size_t)(r + 8) * Ntot + cc] = h1;
            *(uint32_t*)&Clo[(size_t)(r + 8) * Ntot + cc] = l1;
            if (cc >= 2 * DIM) {
                int vc = cc - 2 * DIM;
                *(uint32_t*)&Cv16[(size_t)r * DIM + vc]       = pack_f16(v0x, v0y);
                *(uint32_t*)&Cv16[(size_t)(r + 8) * DIM + vc] = pack_f16(v1x, v1y);
            }
        }
    }
}

// ---------------------------------------------------------------------------
// Single-term fp16 GEMM: out = A(fp16)[M,K] @ Bt(fp16)[N,K]^T + bias (fp32).
// 64x128 tile, BK=64, single 24KB buffer, 8 warps 2m x 4n (warp 32x32).
// ---------------------------------------------------------------------------
#define GF_SMEM 24576

__global__ __launch_bounds__(256, 2) void gemm_f16(
    const __half* __restrict__ A, const __half* __restrict__ Bt,
    float* __restrict__ C, int Mtot, int Ntot, int Ktot,
    const float* __restrict__ bias)
{
    extern __shared__ char smem[];
    const uint32_t sb = smem_u32(smem);
    const int tid  = threadIdx.x;
    const int wid  = tid >> 5;
    const int lane = tid & 31;
    const int row0 = blockIdx.y * 64, col0 = blockIdx.x * 128;

    const int m0 = (wid & 1) * 32;
    const int n0 = (wid >> 1) * 32;

    const uint32_t sA = sb;            // 64 rows x 128B = 8KB
    const uint32_t sB = sb + 8192;     // 128 rows x 128B = 16KB

    float acc[2][4][4] = {};
    const int nchunks = Ktot >> 6;

    for (int c = 0; c < nchunks; c++) {
        #pragma unroll
        for (int i = 0; i < 6; i++) {
            if (i < 2) {
                int local = tid + i * 256;          // 0..511
                int r = local >> 3, seg = local & 7;
                cp16(sA + SWZ(r, seg),
                     A + (size_t)(row0 + r) * Ktot + c * 64 + seg * 8);
            } else {
                int local = tid + (i - 2) * 256;    // 0..1023
                int r = local >> 3, seg = local & 7;
                cp16(sB + SWZ(r, seg),
                     Bt + (size_t)(col0 + r) * Ktot + c * 64 + seg * 8);
            }
        }
        CP_WAIT_ALL();
        __syncthreads();

        #pragma unroll
        for (int ks = 0; ks < 4; ks++) {
            uint32_t aH[2][4];
            #pragma unroll
            for (int mt = 0; mt < 2; mt++) {
                int r   = m0 + mt * 16 + (lane & 15);
                int seg = ks * 2 + (lane >> 4);
                ldsm_x4(aH[mt], sA + SWZ(r, seg));
            }
            #pragma unroll
            for (int np = 0; np < 2; np++) {
                int nr  = n0 + np * 16 + ((lane >> 4) << 3) + (lane & 7);
                int seg = ks * 2 + ((lane >> 3) & 1);
                uint32_t bH[4];
                ldsm_x4(bH, sB + SWZ(nr, seg));
                #pragma unroll
                for (int mt = 0; mt < 2; mt++) {
                    mma_f16(acc[mt][np * 2],     aH[mt], bH);
                    mma_f16(acc[mt][np * 2 + 1], aH[mt], bH + 2);
                }
            }
        }
        __syncthreads();
    }

    #pragma unroll
    for (int mt = 0; mt < 2; mt++) {
        int r = row0 + m0 + mt * 16 + (lane >> 2);
        #pragma unroll
        for (int nt = 0; nt < 4; nt++) {
            int cc = col0 + n0 + nt * 8 + (lane & 3) * 2;
            float bx = bias[cc], by = bias[cc + 1];
            *(float2*)&C[(size_t)r * Ntot + cc] =
                make_float2(acc[mt][nt][0] + bx, acc[mt][nt][1] + by);
            *(float2*)&C[(size_t)(r + 8) * Ntot + cc] =
                make_float2(acc[mt][nt][2] + bx, acc[mt][nt][3] + by);
        }
    }
}

// ---------------------------------------------------------------------------
// Paired-tile flash attention. QK^T: 3-term split bf16 (amplified path).
// PV: single-term fp16 (post-softmax, unamplified). Output fp16.
// smem 56KB: Q1 hi/lo, Q2 hi/lo (32K) + K hi/lo (16K) + V fp16 (8K).
// ---------------------------------------------------------------------------
#define AT_SMEM 57344

__global__ __launch_bounds__(128, 2) void attn_mma(
    const __nv_bfloat16* __restrict__ qkv_hi,
    const __nv_bfloat16* __restrict__ qkv_lo,
    const __half* __restrict__ v_f16,
    __half* __restrict__ out_f16)
{
    extern __shared__ char smem[];
    const uint32_t sb = smem_u32(smem);
    const uint32_t sQ1h = sb,         sQ1l = sb + 8192;
    const uint32_t sQ2h = sb + 16384, sQ2l = sb + 24576;
    const uint32_t sKh  = sb + 32768, sKl  = sb + 40960;
    const uint32_t sV   = sb + 49152;

    const int tid = threadIdx.x, wid = tid >> 5, lane = tid & 31;
    const int t1 = blockIdx.x;
    const int t2 = (NTILES - 1) - t1;
    const int h  = blockIdx.y;
    const int hoff = h * DHEAD;

    #pragma unroll
    for (int i = 0; i < 4; i++) {
        int idx = tid + i * 128;
        int r = idx >> 3, seg = idx & 7;
        uint32_t off = SWZ(r, seg);
        size_t g1 = (size_t)(t1 * 64 + r) * QKV_N + hoff + seg * 8;
        size_t g2 = (size_t)(t2 * 64 + r) * QKV_N + hoff + seg * 8;
        cp16(sQ1h + off, qkv_hi + g1);
        cp16(sQ1l + off, qkv_lo + g1);
        cp16(sQ2h + off, qkv_hi + g2);
        cp16(sQ2l + off, qkv_lo + g2);
    }

    float o1[8][4] = {}, o2[8][4] = {};
    float m1[2] = {-1e30f, -1e30f}, l1[2] = {0.f, 0.f};
    float m2[2] = {-1e30f, -1e30f}, l2[2] = {0.f, 0.f};

    const int rloc = wid * 16 + (lane >> 2);
    const int rA1 = t1 * 64 + rloc;
    const int rA2 = t2 * 64 + rloc;

    auto process = [&](uint32_t sQh, uint32_t sQl, float (*o)[4],
                       float* m_i, float* l_i, int rA, bool maskit, int k0) {
        // S = Q K^T (3-term split bf16)
        float s[8][4] = {};
        #pragma unroll
        for (int ks = 0; ks < 4; ks++) {
            uint32_t aH[4], aL[4];
            {
                int r   = wid * 16 + (lane & 15);
                int seg = ks * 2 + (lane >> 4);
                ldsm_x4(aH, sQh + SWZ(r, seg));
                ldsm_x4(aL, sQl + SWZ(r, seg));
            }
            #pragma unroll
            for (int np = 0; np < 4; np++) {
                int nr = np * 16 + ((lane >> 4) << 3) + (lane & 7);
                int sg = ks * 2 + ((lane >> 3) & 1);
                uint32_t off = SWZ(nr, sg);
                uint32_t bH[4], bL[4];
                ldsm_x4(bH, sKh + off);
                ldsm_x4(bL, sKl + off);
                mma_bf16(s[np * 2],     aH, bH);
                mma_bf16(s[np * 2 + 1], aH, bH + 2);
                mma_bf16(s[np * 2],     aH, bL);
                mma_bf16(s[np * 2 + 1], aH, bL + 2);
                mma_bf16(s[np * 2],     aL, bH);
                mma_bf16(s[np * 2 + 1], aL, bH + 2);
            }
        }

        // scale + causal mask
        #pragma unroll
        for (int j = 0; j < 8; j++) {
            s[j][0] *= 0.125f; s[j][1] *= 0.125f;
            s[j][2] *= 0.125f; s[j][3] *= 0.125f;
        }
        if (maskit) {
            #pragma unroll
            for (int j = 0; j < 8; j++) {
                int col = k0 + j * 8 + (lane & 3) * 2;
                if (col > rA)         s[j][0] = -1e30f;
                if (col + 1 > rA)     s[j][1] = -1e30f;
                if (col > rA + 8)     s[j][2] = -1e30f;
                if (col + 1 > rA + 8) s[j][3] = -1e30f;
            }
        }

        // online softmax on fragments
        float mxA = -1e30f, mxB = -1e30f;
        #pragma unroll
        for (int j = 0; j < 8; j++) {
            mxA = fmaxf(mxA, fmaxf(s[j][0], s[j][1]));
            mxB = fmaxf(mxB, fmaxf(s[j][2], s[j][3]));
        }
        mxA = fmaxf(mxA, __shfl_xor_sync(0xffffffffu, mxA, 1));
        mxA = fmaxf(mxA, __shfl_xor_sync(0xffffffffu, mxA, 2));
        mxB = fmaxf(mxB, __shfl_xor_sync(0xffffffffu, mxB, 1));
        mxB = fmaxf(mxB, __shfl_xor_sync(0xffffffffu, mxB, 2));

        float mA = fmaxf(m_i[0], mxA), mB = fmaxf(m_i[1], mxB);
        float scA = __expf(m_i[0] - mA), scB = __expf(m_i[1] - mB);
        float lA = 0.f, lB = 0.f;
        #pragma unroll
        for (int j = 0; j < 8; j++) {
            s[j][0] = __expf(s[j][0] - mA);
            s[j][1] = __expf(s[j][1] - mA);
            s[j][2] = __expf(s[j][2] - mB);
            s[j][3] = __expf(s[j][3] - mB);
            lA += s[j][0] + s[j][1];
            lB += s[j][2] + s[j][3];
        }
        lA += __shfl_xor_sync(0xffffffffu, lA, 1);
        lA += __shfl_xor_sync(0xffffffffu, lA, 2);
        lB += __shfl_xor_sync(0xffffffffu, lB, 1);
        lB += __shfl_xor_sync(0xffffffffu, lB, 2);
        l_i[0] = l_i[0] * scA + lA;  m_i[0] = mA;
        l_i[1] = l_i[1] * scB + lB;  m_i[1] = mB;
        #pragma unroll
        for (int j = 0; j < 8; j++) {
            o[j][0] *= scA; o[j][1] *= scA;
            o[j][2] *= scB; o[j][3] *= scB;
        }

        // O += P V  (single-term fp16: unamplified post-softmax path)
        #pragma unroll
        for (int t = 0; t < 4; t++) {
            uint32_t pH[4];
            pH[0] = pack_f16(s[2 * t][0],     s[2 * t][1]);
            pH[1] = pack_f16(s[2 * t][2],     s[2 * t][3]);
            pH[2] = pack_f16(s[2 * t + 1][0], s[2 * t + 1][1]);
            pH[3] = pack_f16(s[2 * t + 1][2], s[2 * t + 1][3]);
            #pragma unroll
            for (int sp = 0; sp < 4; sp++) {
                int g  = lane >> 3, rr = lane & 7;
                uint32_t off = SWZ(t * 16 + rr + ((g & 1) << 3),
                                   sp * 2 + (g >> 1));
                uint32_t bH[4];
                ldsm_x4_t(bH, sV + off);
                mma_f16(o[sp * 2],     pH, bH);
                mma_f16(o[sp * 2 + 1], pH, bH + 2);
            }
        }
    };

    for (int kt = 0; kt <= t2; kt++) {
        const int k0 = kt * 64;

        #pragma unroll
        for (int i = 0; i < 4; i++) {
            int idx = tid + i * 128;
            int r = idx >> 3, seg = idx & 7;
            uint32_t off = SWZ(r, seg);
            size_t gk = (size_t)(k0 + r) * QKV_N + DIM + hoff + seg * 8;
            cp16(sKh + off, qkv_hi + gk);
            cp16(sKl + off, qkv_lo + gk);
            cp16(sV + off, v_f16 + (size_t)(k0 + r) * DIM + hoff + seg * 8);
        }
        CP_WAIT_ALL();
        __syncthreads();

        process(sQ2h, sQ2l, o2, m2, l2, rA2, kt == t2, k0);
        if (kt <= t1)
            process(sQ1h, sQ1l, o1, m1, l1, rA1, kt == t1, k0);

        __syncthreads();
    }

    // epilogue: normalize, write fp16
    {
        float invA = 1.0f / l2[0], invB = 1.0f / l2[1];
        #pragma unroll
        for (int j = 0; j < 8; j++) {
            int d = hoff + j * 8 + (lane & 3) * 2;
            *(uint32_t*)&out_f16[(size_t)rA2 * DIM + d] =
                pack_f16(o2[j][0] * invA, o2[j][1] * invA);
            *(uint32_t*)&out_f16[(size_t)(rA2 + 8) * DIM + d] =
                pack_f16(o2[j][2] * invB, o2[j][3] * invB);
        }
    }
    {
        float invA = 1.0f / l1[0], invB = 1.0f / l1[1];
        #pragma unroll
        for (int j = 0; j < 8; j++) {
            int d = hoff + j * 8 + (lane & 3) * 2;
            *(uint32_t*)&out_f16[(size_t)rA1 * DIM + d] =
                pack_f16(o1[j][0] * invA, o1[j][1] * invA);
            *(uint32_t*)&out_f16[(size_t)(rA1 + 8) * DIM + d] =
                pack_f16(o1[j][2] * invB, o1[j][3] * invB);
        }
    }
}

// ---------------------------------------------------------------------------
extern "C" void kernel_launch(void* const* d_in, const int* in_sizes, int n_in,
                              void* d_out, int out_size)
{
    const float* x    = (const float*)d_in[0];
    const float* Wqkv = (const float*)d_in[1];
    const float* Wout = (const float*)d_in[2];
    const float* bias = (const float*)d_in[3];
    float* out = (float*)d_out;

    __nv_bfloat16 *xh, *xl, *wqh, *wql, *qh, *ql;
    __half *vf, *wof, *af;
    cudaGetSymbolAddress((void**)&xh,  g_x_hi);
    cudaGetSymbolAddress((void**)&xl,  g_x_lo);
    cudaGetSymbolAddress((void**)&wqh, g_wqkv_hi);
    cudaGetSymbolAddress((void**)&wql, g_wqkv_lo);
    cudaGetSymbolAddress((void**)&qh,  g_qkv_hi);
    cudaGetSymbolAddress((void**)&ql,  g_qkv_lo);
    cudaGetSymbolAddress((void**)&vf,  g_v_f16);
    cudaGetSymbolAddress((void**)&wof, g_wout_f16);
    cudaGetSymbolAddress((void**)&af,  g_attn_f16);

    cudaFuncSetAttribute(gemm_mma, cudaFuncAttributeMaxDynamicSharedMemorySize,
                         G_SMEM);
    cudaFuncSetAttribute(gemm_f16, cudaFuncAttributeMaxDynamicSharedMemorySize,
                         GF_SMEM);
    cudaFuncSetAttribute(attn_mma, cudaFuncAttributeMaxDynamicSharedMemorySize,
                         AT_SMEM);

    // Prep
    split_kernel<<<SEQ * DIM / 1024, 256>>>(x, xh, xl);
    tsplit_kernel<<<dim3(QKV_N / 32, DIM / 32), dim3(32, 8)>>>(Wqkv, wqh, wql,
                                                               DIM, QKV_N);
    tconv_f16_kernel<<<dim3(DIM / 32, DIM / 32), dim3(32, 8)>>>(Wout, wof,
                                                                DIM, DIM);

    // 1) qkv = x @ Wqkv  -> bf16 hi/lo + fp16 V copy
    gemm_mma<<<dim3(QKV_N / 128, SEQ / 128), 256, G_SMEM>>>(
        xh, xl, wqh, wql, qh, ql, vf, SEQ, QKV_N, DIM);

    // 2) attention (paired tiles, PV fp16) -> fp16
    attn_mma<<<dim3(NTILES / 2, NHEAD), 128, AT_SMEM>>>(qh, ql, vf, af);

    // 3) out = attn @ Wout + bias  (single-term fp16, fp32 out)
    gemm_f16<<<dim3(DIM / 128, SEQ / 64), 256, GF_SMEM>>>(
        af, wof, out, SEQ, DIM, DIM, bias);
}

// round 11
// speedup vs baseline: 1.3487x; 1.0751x over previous
#include <cuda_runtime.h>
#include <cuda_bf16.h>
#include <cuda_fp16.h>
#include <cstdint>

#define SEQ 2048
#define DIM 1024
#define NHEAD 16
#define DHEAD 64
#define QKV_N (3 * DIM)   // 3072
#define QK_N (2 * DIM)    // 2048 (Q and K columns only)
#define NTILES (SEQ / 64) // 32

// ---------------------------------------------------------------------------
// Scratch (device globals — allocation-free rule)
// ---------------------------------------------------------------------------
__device__ __nv_bfloat16 g_x_hi[SEQ * DIM];
__device__ __nv_bfloat16 g_x_lo[SEQ * DIM];
__device__ __half        g_x_f16[SEQ * DIM];
__device__ __nv_bfloat16 g_wqk_hi[QK_N * DIM];     // [N,K] transposed, QK cols
__device__ __nv_bfloat16 g_wqk_lo[QK_N * DIM];
__device__ __half        g_wvt_f16[DIM * DIM];     // [N,K] transposed, V cols
__device__ __nv_bfloat16 g_qk_hi[SEQ * QK_N];      // Q,K split bf16
__device__ __nv_bfloat16 g_qk_lo[SEQ * QK_N];
__device__ __half        g_v_f16[SEQ * DIM];       // V fp16
__device__ __half        g_wout_f16[DIM * DIM];    // [N,K] transposed, fp16
__device__ __half        g_attn_f16[SEQ * DIM];    // attention output, fp16

// ---------------------------------------------------------------------------
// PTX helpers
// ---------------------------------------------------------------------------
__device__ __forceinline__ uint32_t smem_u32(const void* p) {
    uint32_t a;
    asm("{ .reg .u64 t; cvta.to.shared.u64 t, %1; cvt.u32.u64 %0, t; }"
        : "=r"(a) : "l"(p));
    return a;
}

__device__ __forceinline__ void ldsm_x4(uint32_t* r, uint32_t addr) {
    asm volatile("ldmatrix.sync.aligned.m8n8.x4.shared.b16 {%0,%1,%2,%3}, [%4];"
                 : "=r"(r[0]), "=r"(r[1]), "=r"(r[2]), "=r"(r[3]) : "r"(addr));
}

__device__ __forceinline__ void ldsm_x4_t(uint32_t* r, uint32_t addr) {
    asm volatile("ldmatrix.sync.aligned.m8n8.x4.trans.shared.b16 {%0,%1,%2,%3}, [%4];"
                 : "=r"(r[0]), "=r"(r[1]), "=r"(r[2]), "=r"(r[3]) : "r"(addr));
}

__device__ __forceinline__ void mma_bf16(float* d, const uint32_t* a,
                                         const uint32_t* b) {
    asm("mma.sync.aligned.m16n8k16.row.col.f32.bf16.bf16.f32 "
        "{%0,%1,%2,%3}, {%4,%5,%6,%7}, {%8,%9}, {%0,%1,%2,%3};"
        : "+f"(d[0]), "+f"(d[1]), "+f"(d[2]), "+f"(d[3])
        : "r"(a[0]), "r"(a[1]), "r"(a[2]), "r"(a[3]), "r"(b[0]), "r"(b[1]));
}

__device__ __forceinline__ void mma_f16(float* d, const uint32_t* a,
                                        const uint32_t* b) {
    asm("mma.sync.aligned.m16n8k16.row.col.f32.f16.f16.f32 "
        "{%0,%1,%2,%3}, {%4,%5,%6,%7}, {%8,%9}, {%0,%1,%2,%3};"
        : "+f"(d[0]), "+f"(d[1]), "+f"(d[2]), "+f"(d[3])
        : "r"(a[0]), "r"(a[1]), "r"(a[2]), "r"(a[3]), "r"(b[0]), "r"(b[1]));
}

__device__ __forceinline__ void cp16(uint32_t dst, const void* src) {
    asm volatile("cp.async.cg.shared.global [%0], [%1], 16;"
                 :: "r"(dst), "l"(src));
}
#define CP_WAIT_ALL() asm volatile("cp.async.wait_all;" ::: "memory")

// swizzled smem byte offset for (row, 16B-seg), 128B rows (8 segs)
#define SWZ(r, seg) ((uint32_t)((r) * 128 + (((seg) ^ ((r) & 7)) << 4)))

// pack 2 floats into bf16x2 hi + residual bf16x2 lo
__device__ __forceinline__ void split_pack(float x, float y,
                                           uint32_t& hi, uint32_t& lo) {
    __nv_bfloat162 h = __floats2bfloat162_rn(x, y);
    float2 hf = __bfloat1622float2(h);
    __nv_bfloat162 l = __floats2bfloat162_rn(x - hf.x, y - hf.y);
    hi = *reinterpret_cast<uint32_t*>(&h);
    lo = *reinterpret_cast<uint32_t*>(&l);
}

__device__ __forceinline__ uint32_t pack_f16(float x, float y) {
    __half2 h = __floats2half2_rn(x, y);
    return *reinterpret_cast<uint32_t*>(&h);
}

// ---------------------------------------------------------------------------
// Elementwise split: fp32 -> bf16 hi + bf16 lo + fp16 copy
// ---------------------------------------------------------------------------
__global__ __launch_bounds__(256) void split_kernel(
    const float* __restrict__ in,
    __nv_bfloat16* __restrict__ hi, __nv_bfloat16* __restrict__ lo,
    __half* __restrict__ f16)
{
    int i = (blockIdx.x * 256 + threadIdx.x) * 4;
    float4 v = *(const float4*)(in + i);
    uint32_t h0, l0, h1, l1;
    split_pack(v.x, v.y, h0, l0);
    split_pack(v.z, v.w, h1, l1);
    *(uint32_t*)(hi + i)     = h0;
    *(uint32_t*)(hi + i + 2) = h1;
    *(uint32_t*)(lo + i)     = l0;
    *(uint32_t*)(lo + i + 2) = l1;
    *(uint32_t*)(f16 + i)     = pack_f16(v.x, v.y);
    *(uint32_t*)(f16 + i + 2) = pack_f16(v.z, v.w);
}

// ---------------------------------------------------------------------------
// Transpose + split (bf16 hi/lo): W[K,N] fp32 -> Wt[N,K]. 32x32 tiles.
// N is the row stride of W; grid.x limits which columns are processed.
// ---------------------------------------------------------------------------
__global__ __launch_bounds__(256) void tsplit_kernel(
    const float* __restrict__ W,
    __nv_bfloat16* __restrict__ hi, __nv_bfloat16* __restrict__ lo,
    int K, int N)
{
    __shared__ float t[32][33];
    const int n0 = blockIdx.x * 32, k0 = blockIdx.y * 32;
    const int tx = threadIdx.x, ty = threadIdx.y;   // 32 x 8

    #pragma unroll
    for (int j = 0; j < 4; j++)
        t[ty + 8 * j][tx] = W[(size_t)(k0 + ty + 8 * j) * N + n0 + tx];
    __syncthreads();

    #pragma unroll
    for (int j = 0; j < 4; j++) {
        int row = ty + 8 * j;
        float v = t[tx][row];
        __nv_bfloat16 h = __float2bfloat16(v);
        size_t o = (size_t)(n0 + row) * K + k0 + tx;
        hi[o] = h;
        lo[o] = __float2bfloat16(v - __bfloat162float(h));
    }
}

// ---------------------------------------------------------------------------
// Transpose + convert (fp16): W[K,N-stride] fp32 -> Wt[n,K]. 32x32 tiles.
// Pass W pre-offset to select a column window.
// ---------------------------------------------------------------------------
__global__ __launch_bounds__(256) void tconv_f16_kernel(
    const float* __restrict__ W, __half* __restrict__ out, int K, int N)
{
    __shared__ float t[32][33];
    const int n0 = blockIdx.x * 32, k0 = blockIdx.y * 32;
    const int tx = threadIdx.x, ty = threadIdx.y;

    #pragma unroll
    for (int j = 0; j < 4; j++)
        t[ty + 8 * j][tx] = W[(size_t)(k0 + ty + 8 * j) * N + n0 + tx];
    __syncthreads();

    #pragma unroll
    for (int j = 0; j < 4; j++) {
        int row = ty + 8 * j;
        out[(size_t)(n0 + row) * K + k0 + tx] = __float2half(t[tx][row]);
    }
}

// ---------------------------------------------------------------------------
// Split-bf16 tensor-core GEMM (3 terms, fp32 accum). R5-proven config:
// 128x128 tile, BK=64, single 64KB buffer, 8 warps 4m x 2n, 2 CTAs/SM.
// Computes the QK columns only; outputs bf16 hi/lo split.
// ---------------------------------------------------------------------------
#define G_SMEM (4 * 16384)

__global__ __launch_bounds__(256, 2) void gemm_mma(
    const __nv_bfloat16* __restrict__ Ahi, const __nv_bfloat16* __restrict__ Alo,
    const __nv_bfloat16* __restrict__ Bhi, const __nv_bfloat16* __restrict__ Blo,
    __nv_bfloat16* __restrict__ Chi, __nv_bfloat16* __restrict__ Clo,
    int Mtot, int Ntot, int Ktot)
{
    extern __shared__ char smem[];
    const uint32_t sb = smem_u32(smem);
    const int tid  = threadIdx.x;
    const int wid  = tid >> 5;
    const int lane = tid & 31;
    const int row0 = blockIdx.y * 128, col0 = blockIdx.x * 128;

    const int m0 = (wid & 3) * 32;
    const int n0 = (wid >> 2) * 64;

    const uint32_t sA  = sb;
    const uint32_t sAL = sb + 16384;
    const uint32_t sB  = sb + 32768;
    const uint32_t sBL = sb + 49152;

    float acc[2][8][4] = {};

    const int nchunks = Ktot >> 6;
    for (int c = 0; c < nchunks; c++) {
        #pragma unroll
        for (int i = 0; i < 16; i++) {
            const int tile = i >> 2;
            int idx = tid + i * 256;
            int r   = (idx >> 3) & 127;
            int seg = idx & 7;
            const __nv_bfloat16* src;
            if (tile == 0)      src = Ahi + (size_t)(row0 + r) * Ktot;
            else if (tile == 1) src = Alo + (size_t)(row0 + r) * Ktot;
            else if (tile == 2) src = Bhi + (size_t)(col0 + r) * Ktot;
            else                src = Blo + (size_t)(col0 + r) * Ktot;
            cp16(sb + tile * 16384 + SWZ(r, seg), src + c * 64 + seg * 8);
        }
        CP_WAIT_ALL();
        __syncthreads();

        #pragma unroll
        for (int ks = 0; ks < 4; ks++) {
            uint32_t aH[2][4], aL[2][4];
            #pragma unroll
            for (int mt = 0; mt < 2; mt++) {
                int r   = m0 + mt * 16 + (lane & 15);
                int seg = ks * 2 + (lane >> 4);
                uint32_t off = SWZ(r, seg);
                ldsm_x4(aH[mt], sA  + off);
                ldsm_x4(aL[mt], sAL + off);
            }
            #pragma unroll
            for (int np = 0; np < 4; np++) {
                int nr  = n0 + np * 16 + ((lane >> 4) << 3) + (lane & 7);
                int seg = ks * 2 + ((lane >> 3) & 1);
                uint32_t off = SWZ(nr, seg);
                uint32_t bH[4], bL[4];
                ldsm_x4(bH, sB  + off);
                ldsm_x4(bL, sBL + off);
                #pragma unroll
                for (int mt = 0; mt < 2; mt++) {
                    mma_bf16(acc[mt][np * 2],     aH[mt], bH);
                    mma_bf16(acc[mt][np * 2 + 1], aH[mt], bH + 2);
                    mma_bf16(acc[mt][np * 2],     aH[mt], bL);
                    mma_bf16(acc[mt][np * 2 + 1], aH[mt], bL + 2);
                    mma_bf16(acc[mt][np * 2],     aL[mt], bH);
                    mma_bf16(acc[mt][np * 2 + 1], aL[mt], bH + 2);
                }
            }
        }
        __syncthreads();
    }

    #pragma unroll
    for (int mt = 0; mt < 2; mt++) {
        int r = row0 + m0 + mt * 16 + (lane >> 2);
        #pragma unroll
        for (int nt = 0; nt < 8; nt++) {
            int cc = col0 + n0 + nt * 8 + (lane & 3) * 2;
            uint32_t h0, l0, h1, l1;
            split_pack(acc[mt][nt][0], acc[mt][nt][1], h0, l0);
            split_pack(acc[mt][nt][2], acc[mt][nt][3], h1, l1);
            *(uint32_t*)&Chi[(size_t)r * Ntot + cc]       = h0;
            *(uint32_t*)&Clo[(size_t)r * Ntot + cc]       = l0;
            *(uint32_t*)&Chi[(size_t)(r + 8) * Ntot + cc] = h1;
            *(uint32_t*)&Clo[(size_t)(r + 8) * Ntot + cc] = l1;
        }
    }
}

// ---------------------------------------------------------------------------
// Single-term fp16 GEMM: A(fp16)[M,K] @ Bt(fp16)[N,K]^T (+bias if non-null).
// Output fp32 C, or fp16 C16 if non-null.
// 64x128 tile, BK=64, single 24KB buffer, 8 warps 2m x 4n (warp 32x32).
// ---------------------------------------------------------------------------
#define GF_SMEM 24576

__global__ __launch_bounds__(256, 2) void gemm_f16(
    const __half* __restrict__ A, const __half* __restrict__ Bt,
    float* __restrict__ C, __half* __restrict__ C16,
    int Mtot, int Ntot, int Ktot,
    const float* __restrict__ bias)
{
    extern __shared__ char smem[];
    const uint32_t sb = smem_u32(smem);
    const int tid  = threadIdx.x;
    const int wid  = tid >> 5;
    const int lane = tid & 31;
    const int row0 = blockIdx.y * 64, col0 = blockIdx.x * 128;

    const int m0 = (wid & 1) * 32;
    const int n0 = (wid >> 1) * 32;

    const uint32_t sA = sb;            // 64 rows x 128B = 8KB
    const uint32_t sB = sb + 8192;     // 128 rows x 128B = 16KB

    float acc[2][4][4] = {};
    const int nchunks = Ktot >> 6;

    for (int c = 0; c < nchunks; c++) {
        #pragma unroll
        for (int i = 0; i < 6; i++) {
            if (i < 2) {
                int local = tid + i * 256;          // 0..511
                int r = local >> 3, seg = local & 7;
                cp16(sA + SWZ(r, seg),
                     A + (size_t)(row0 + r) * Ktot + c * 64 + seg * 8);
            } else {
                int local = tid + (i - 2) * 256;    // 0..1023
                int r = local >> 3, seg = local & 7;
                cp16(sB + SWZ(r, seg),
                     Bt + (size_t)(col0 + r) * Ktot + c * 64 + seg * 8);
            }
        }
        CP_WAIT_ALL();
        __syncthreads();

        #pragma unroll
        for (int ks = 0; ks < 4; ks++) {
            uint32_t aH[2][4];
            #pragma unroll
            for (int mt = 0; mt < 2; mt++) {
                int r   = m0 + mt * 16 + (lane & 15);
                int seg = ks * 2 + (lane >> 4);
                ldsm_x4(aH[mt], sA + SWZ(r, seg));
            }
            #pragma unroll
            for (int np = 0; np < 2; np++) {
                int nr  = n0 + np * 16 + ((lane >> 4) << 3) + (lane & 7);
                int seg = ks * 2 + ((lane >> 3) & 1);
                uint32_t bH[4];
                ldsm_x4(bH, sB + SWZ(nr, seg));
                #pragma unroll
                for (int mt = 0; mt < 2; mt++) {
                    mma_f16(acc[mt][np * 2],     aH[mt], bH);
                    mma_f16(acc[mt][np * 2 + 1], aH[mt], bH + 2);
                }
            }
        }
        __syncthreads();
    }

    #pragma unroll
    for (int mt = 0; mt < 2; mt++) {
        int r = row0 + m0 + mt * 16 + (lane >> 2);
        #pragma unroll
        for (int nt = 0; nt < 4; nt++) {
            int cc = col0 + n0 + nt * 8 + (lane & 3) * 2;
            float bx = 0.f, by = 0.f;
            if (bias) { bx = bias[cc]; by = bias[cc + 1]; }
            float v0x = acc[mt][nt][0] + bx, v0y = acc[mt][nt][1] + by;
            float v1x = acc[mt][nt][2] + bx, v1y = acc[mt][nt][3] + by;
            if (C16) {
                *(uint32_t*)&C16[(size_t)r * Ntot + cc]       = pack_f16(v0x, v0y);
                *(uint32_t*)&C16[(size_t)(r + 8) * Ntot + cc] = pack_f16(v1x, v1y);
            } else {
                *(float2*)&C[(size_t)r * Ntot + cc]       = make_float2(v0x, v0y);
                *(float2*)&C[(size_t)(r + 8) * Ntot + cc] = make_float2(v1x, v1y);
            }
        }
    }
}

// ---------------------------------------------------------------------------
// Paired-tile flash attention. QK^T: 3-term split bf16 (amplified path).
// PV: single-term fp16. Q/K read from g_qk (stride QK_N), V from g_v_f16.
// smem 56KB: Q1 hi/lo, Q2 hi/lo (32K) + K hi/lo (16K) + V fp16 (8K).
// ---------------------------------------------------------------------------
#define AT_SMEM 57344

__global__ __launch_bounds__(128, 2) void attn_mma(
    const __nv_bfloat16* __restrict__ qk_hi,
    const __nv_bfloat16* __restrict__ qk_lo,
    const __half* __restrict__ v_f16,
    __half* __restrict__ out_f16)
{
    extern __shared__ char smem[];
    const uint32_t sb = smem_u32(smem);
    const uint32_t sQ1h = sb,         sQ1l = sb + 8192;
    const uint32_t sQ2h = sb + 16384, sQ2l = sb + 24576;
    const uint32_t sKh  = sb + 32768, sKl  = sb + 40960;
    const uint32_t sV   = sb + 49152;

    const int tid = threadIdx.x, wid = tid >> 5, lane = tid & 31;
    const int t1 = blockIdx.x;
    const int t2 = (NTILES - 1) - t1;
    const int h  = blockIdx.y;
    const int hoff = h * DHEAD;

    #pragma unroll
    for (int i = 0; i < 4; i++) {
        int idx = tid + i * 128;
        int r = idx >> 3, seg = idx & 7;
        uint32_t off = SWZ(r, seg);
        size_t g1 = (size_t)(t1 * 64 + r) * QK_N + hoff + seg * 8;
        size_t g2 = (size_t)(t2 * 64 + r) * QK_N + hoff + seg * 8;
        cp16(sQ1h + off, qk_hi + g1);
        cp16(sQ1l + off, qk_lo + g1);
        cp16(sQ2h + off, qk_hi + g2);
        cp16(sQ2l + off, qk_lo + g2);
    }

    float o1[8][4] = {}, o2[8][4] = {};
    float m1[2] = {-1e30f, -1e30f}, l1[2] = {0.f, 0.f};
    float m2[2] = {-1e30f, -1e30f}, l2[2] = {0.f, 0.f};

    const int rloc = wid * 16 + (lane >> 2);
    const int rA1 = t1 * 64 + rloc;
    const int rA2 = t2 * 64 + rloc;

    auto process = [&](uint32_t sQh, uint32_t sQl, float (*o)[4],
                       float* m_i, float* l_i, int rA, bool maskit, int k0) {
        // S = Q K^T (3-term split bf16)
        float s[8][4] = {};
        #pragma unroll
        for (int ks = 0; ks < 4; ks++) {
            uint32_t aH[4], aL[4];
            {
                int r   = wid * 16 + (lane & 15);
                int seg = ks * 2 + (lane >> 4);
                ldsm_x4(aH, sQh + SWZ(r, seg));
                ldsm_x4(aL, sQl + SWZ(r, seg));
            }
            #pragma unroll
            for (int np = 0; np < 4; np++) {
                int nr = np * 16 + ((lane >> 4) << 3) + (lane & 7);
                int sg = ks * 2 + ((lane >> 3) & 1);
                uint32_t off = SWZ(nr, sg);
                uint32_t bH[4], bL[4];
                ldsm_x4(bH, sKh + off);
                ldsm_x4(bL, sKl + off);
                mma_bf16(s[np * 2],     aH, bH);
                mma_bf16(s[np * 2 + 1], aH, bH + 2);
                mma_bf16(s[np * 2],     aH, bL);
                mma_bf16(s[np * 2 + 1], aH, bL + 2);
                mma_bf16(s[np * 2],     aL, bH);
                mma_bf16(s[np * 2 + 1], aL, bH + 2);
            }
        }

        // scale + causal mask
        #pragma unroll
        for (int j = 0; j < 8; j++) {
            s[j][0] *= 0.125f; s[j][1] *= 0.125f;
            s[j][2] *= 0.125f; s[j][3] *= 0.125f;
        }
        if (maskit) {
            #pragma unroll
            for (int j = 0; j < 8; j++) {
                int col = k0 + j * 8 + (lane & 3) * 2;
                if (col > rA)         s[j][0] = -1e30f;
                if (col + 1 > rA)     s[j][1] = -1e30f;
                if (col > rA + 8)     s[j][2] = -1e30f;
                if (col + 1 > rA + 8) s[j][3] = -1e30f;
            }
        }

        // online softmax on fragments
        float mxA = -1e30f, mxB = -1e30f;
        #pragma unroll
        for (int j = 0; j < 8; j++) {
            mxA = fmaxf(mxA, fmaxf(s[j][0], s[j][1]));
            mxB = fmaxf(mxB, fmaxf(s[j][2], s[j][3]));
        }
        mxA = fmaxf(mxA, __shfl_xor_sync(0xffffffffu, mxA, 1));
        mxA = fmaxf(mxA, __shfl_xor_sync(0xffffffffu, mxA, 2));
        mxB = fmaxf(mxB, __shfl_xor_sync(0xffffffffu, mxB, 1));
        mxB = fmaxf(mxB, __shfl_xor_sync(0xffffffffu, mxB, 2));

        float mA = fmaxf(m_i[0], mxA), mB = fmaxf(m_i[1], mxB);
        float scA = __expf(m_i[0] - mA), scB = __expf(m_i[1] - mB);
        float lA = 0.f, lB = 0.f;
        #pragma unroll
        for (int j = 0; j < 8; j++) {
            s[j][0] = __expf(s[j][0] - mA);
            s[j][1] = __expf(s[j][1] - mA);
            s[j][2] = __expf(s[j][2] - mB);
            s[j][3] = __expf(s[j][3] - mB);
            lA += s[j][0] + s[j][1];
            lB += s[j][2] + s[j][3];
        }
        lA += __shfl_xor_sync(0xffffffffu, lA, 1);
        lA += __shfl_xor_sync(0xffffffffu, lA, 2);
        lB += __shfl_xor_sync(0xffffffffu, lB, 1);
        lB += __shfl_xor_sync(0xffffffffu, lB, 2);
        l_i[0] = l_i[0] * scA + lA;  m_i[0] = mA;
        l_i[1] = l_i[1] * scB + lB;  m_i[1] = mB;
        #pragma unroll
        for (int j = 0; j < 8; j++) {
            o[j][0] *= scA; o[j][1] *= scA;
            o[j][2] *= scB; o[j][3] *= scB;
        }

        // O += P V  (single-term fp16)
        #pragma unroll
        for (int t = 0; t < 4; t++) {
            uint32_t pH[4];
            pH[0] = pack_f16(s[2 * t][0],     s[2 * t][1]);
            pH[1] = pack_f16(s[2 * t][2],     s[2 * t][3]);
            pH[2] = pack_f16(s[2 * t + 1][0], s[2 * t + 1][1]);
            pH[3] = pack_f16(s[2 * t + 1][2], s[2 * t + 1][3]);
            #pragma unroll
            for (int sp = 0; sp < 4; sp++) {
                int g  = lane >> 3, rr = lane & 7;
                uint32_t off = SWZ(t * 16 + rr + ((g & 1) << 3),
                                   sp * 2 + (g >> 1));
                uint32_t bH[4];
                ldsm_x4_t(bH, sV + off);
                mma_f16(o[sp * 2],     pH, bH);
                mma_f16(o[sp * 2 + 1], pH, bH + 2);
            }
        }
    };

    for (int kt = 0; kt <= t2; kt++) {
        const int k0 = kt * 64;

        #pragma unroll
        for (int i = 0; i < 4; i++) {
            int idx = tid + i * 128;
            int r = idx >> 3, seg = idx & 7;
            uint32_t off = SWZ(r, seg);
            size_t gk = (size_t)(k0 + r) * QK_N + DIM + hoff + seg * 8;
            cp16(sKh + off, qk_hi + gk);
            cp16(sKl + off, qk_lo + gk);
            cp16(sV + off, v_f16 + (size_t)(k0 + r) * DIM + hoff + seg * 8);
        }
        CP_WAIT_ALL();
        __syncthreads();

        process(sQ2h, sQ2l, o2, m2, l2, rA2, kt == t2, k0);
        if (kt <= t1)
            process(sQ1h, sQ1l, o1, m1, l1, rA1, kt == t1, k0);

        __syncthreads();
    }

    // epilogue: normalize, write fp16
    {
        float invA = 1.0f / l2[0], invB = 1.0f / l2[1];
        #pragma unroll
        for (int j = 0; j < 8; j++) {
            int d = hoff + j * 8 + (lane & 3) * 2;
            *(uint32_t*)&out_f16[(size_t)rA2 * DIM + d] =
                pack_f16(o2[j][0] * invA, o2[j][1] * invA);
            *(uint32_t*)&out_f16[(size_t)(rA2 + 8) * DIM + d] =
                pack_f16(o2[j][2] * invB, o2[j][3] * invB);
        }
    }
    {
        float invA = 1.0f / l1[0], invB = 1.0f / l1[1];
        #pragma unroll
        for (int j = 0; j < 8; j++) {
            int d = hoff + j * 8 + (lane & 3) * 2;
            *(uint32_t*)&out_f16[(size_t)rA1 * DIM + d] =
                pack_f16(o1[j][0] * invA, o1[j][1] * invA);
            *(uint32_t*)&out_f16[(size_t)(rA1 + 8) * DIM + d] =
                pack_f16(o1[j][2] * invB, o1[j][3] * invB);
        }
    }
}

// ---------------------------------------------------------------------------
extern "C" void kernel_launch(void* const* d_in, const int* in_sizes, int n_in,
                              void* d_out, int out_size)
{
    const float* x    = (const float*)d_in[0];
    const float* Wqkv = (const float*)d_in[1];
    const float* Wout = (const float*)d_in[2];
    const float* bias = (const float*)d_in[3];
    float* out = (float*)d_out;

    __nv_bfloat16 *xh, *xl, *wqh, *wql, *qh, *ql;
    __half *xf, *wvt, *vf, *wof, *af;
    cudaGetSymbolAddress((void**)&xh,  g_x_hi);
    cudaGetSymbolAddress((void**)&xl,  g_x_lo);
    cudaGetSymbolAddress((void**)&xf,  g_x_f16);
    cudaGetSymbolAddress((void**)&wqh, g_wqk_hi);
    cudaGetSymbolAddress((void**)&wql, g_wqk_lo);
    cudaGetSymbolAddress((void**)&wvt, g_wvt_f16);
    cudaGetSymbolAddress((void**)&qh,  g_qk_hi);
    cudaGetSymbolAddress((void**)&ql,  g_qk_lo);
    cudaGetSymbolAddress((void**)&vf,  g_v_f16);
    cudaGetSymbolAddress((void**)&wof, g_wout_f16);
    cudaGetSymbolAddress((void**)&af,  g_attn_f16);

    cudaFuncSetAttribute(gemm_mma, cudaFuncAttributeMaxDynamicSharedMemorySize,
                         G_SMEM);
    cudaFuncSetAttribute(gemm_f16, cudaFuncAttributeMaxDynamicSharedMemorySize,
                         GF_SMEM);
    cudaFuncSetAttribute(attn_mma, cudaFuncAttributeMaxDynamicSharedMemorySize,
                         AT_SMEM);

    // Prep
    split_kernel<<<SEQ * DIM / 1024, 256>>>(x, xh, xl, xf);
    // Wqkv QK columns [0, 2048) -> split bf16 transposed
    tsplit_kernel<<<dim3(QK_N / 32, DIM / 32), dim3(32, 8)>>>(Wqkv, wqh, wql,
                                                              DIM, QKV_N);
    // Wqkv V columns [2048, 3072) -> fp16 transposed (pre-offset pointer)
    tconv_f16_kernel<<<dim3(DIM / 32, DIM / 32), dim3(32, 8)>>>(Wqkv + QK_N,
                                                                wvt, DIM, QKV_N);
    tconv_f16_kernel<<<dim3(DIM / 32, DIM / 32), dim3(32, 8)>>>(Wout, wof,
                                                                DIM, DIM);

    // 1a) Q,K = x @ Wqkv[:, :2048]  (3-term split bf16, grid 16x16)
    gemm_mma<<<dim3(QK_N / 128, SEQ / 128), 256, G_SMEM>>>(
        xh, xl, wqh, wql, qh, ql, SEQ, QK_N, DIM);

    // 1b) V = x @ Wqkv[:, 2048:]  (single fp16, fp16 out)
    gemm_f16<<<dim3(DIM / 128, SEQ / 64), 256, GF_SMEM>>>(
        xf, wvt, nullptr, vf, SEQ, DIM, DIM, nullptr);

    // 2) attention (paired tiles, PV fp16) -> fp16
    attn_mma<<<dim3(NTILES / 2, NHEAD), 128, AT_SMEM>>>(qh, ql, vf, af);

    // 3) out = attn @ Wout + bias  (single fp16, fp32 out)
    gemm_f16<<<dim3(DIM / 128, SEQ / 64), 256, GF_SMEM>>>(
        af, wof, out, nullptr, SEQ, DIM, DIM, bias);
}

// round 15
// speedup vs baseline: 1.3727x; 1.0178x over previous
#include <cuda_runtime.h>
#include <cuda_bf16.h>
#include <cuda_fp16.h>
#include <cstdint>

#define SEQ 2048
#define DIM 1024
#define NHEAD 16
#define DHEAD 64
#define QKV_N (3 * DIM)   // 3072
#define QK_N (2 * DIM)    // 2048
#define NTILES (SEQ / 64) // 32

// ---------------------------------------------------------------------------
// Scratch (device globals — allocation-free rule)
// ---------------------------------------------------------------------------
__device__ __half g_x_hi[SEQ * DIM];      // fp16(x)  (also A for V gemm)
__device__ __half g_x_lo[SEQ * DIM];      // fp16 residual
__device__ __half g_wqk_hi[QK_N * DIM];   // [N,K] transposed, QK cols
__device__ __half g_wqk_lo[QK_N * DIM];
__device__ __half g_wvt_f16[DIM * DIM];   // [N,K] transposed, V cols
__device__ __half g_qk_hi[SEQ * QK_N];    // Q,K fp16 hi
__device__ __half g_qk_lo[SEQ * QK_N];    // Q,K fp16 lo
__device__ __half g_v_f16[SEQ * DIM];     // V fp16
__device__ __half g_wout_f16[DIM * DIM];  // [N,K] transposed
__device__ __half g_attn_f16[SEQ * DIM];  // attention output

// ---------------------------------------------------------------------------
// PTX helpers
// ---------------------------------------------------------------------------
__device__ __forceinline__ uint32_t smem_u32(const void* p) {
    uint32_t a;
    asm("{ .reg .u64 t; cvta.to.shared.u64 t, %1; cvt.u32.u64 %0, t; }"
        : "=r"(a) : "l"(p));
    return a;
}

__device__ __forceinline__ void ldsm_x4(uint32_t* r, uint32_t addr) {
    asm volatile("ldmatrix.sync.aligned.m8n8.x4.shared.b16 {%0,%1,%2,%3}, [%4];"
                 : "=r"(r[0]), "=r"(r[1]), "=r"(r[2]), "=r"(r[3]) : "r"(addr));
}

__device__ __forceinline__ void ldsm_x4_t(uint32_t* r, uint32_t addr) {
    asm volatile("ldmatrix.sync.aligned.m8n8.x4.trans.shared.b16 {%0,%1,%2,%3}, [%4];"
                 : "=r"(r[0]), "=r"(r[1]), "=r"(r[2]), "=r"(r[3]) : "r"(addr));
}

// fp16 inputs, fp32 accumulator (main terms)
__device__ __forceinline__ void mma_f16(float* d, const uint32_t* a,
                                        const uint32_t* b) {
    asm("mma.sync.aligned.m16n8k16.row.col.f32.f16.f16.f32 "
        "{%0,%1,%2,%3}, {%4,%5,%6,%7}, {%8,%9}, {%0,%1,%2,%3};"
        : "+f"(d[0]), "+f"(d[1]), "+f"(d[2]), "+f"(d[3])
        : "r"(a[0]), "r"(a[1]), "r"(a[2]), "r"(a[3]), "r"(b[0]), "r"(b[1]));
}

// fp16 inputs, fp16 accumulator (small cross terms; potentially 2x rate)
__device__ __forceinline__ void mma_f16h(uint32_t* d, const uint32_t* a,
                                         const uint32_t* b) {
    asm("mma.sync.aligned.m16n8k16.row.col.f16.f16.f16.f16 "
        "{%0,%1}, {%2,%3,%4,%5}, {%6,%7}, {%0,%1};"
        : "+r"(d[0]), "+r"(d[1])
        : "r"(a[0]), "r"(a[1]), "r"(a[2]), "r"(a[3]), "r"(b[0]), "r"(b[1]));
}

__device__ __forceinline__ void cp16(uint32_t dst, const void* src) {
    asm volatile("cp.async.cg.shared.global [%0], [%1], 16;"
                 :: "r"(dst), "l"(src));
}
#define CP_WAIT_ALL() asm volatile("cp.async.wait_all;" ::: "memory")

// swizzled smem byte offset for (row, 16B-seg), 128B rows (8 segs)
#define SWZ(r, seg) ((uint32_t)((r) * 128 + (((seg) ^ ((r) & 7)) << 4)))

__device__ __forceinline__ uint32_t pack_f16(float x, float y) {
    __half2 h = __floats2half2_rn(x, y);
    return *reinterpret_cast<uint32_t*>(&h);
}

// pack 2 floats into fp16 hi + fp16 residual lo
__device__ __forceinline__ void split_pack_f16(float x, float y,
                                               uint32_t& hi, uint32_t& lo) {
    __half2 h = __floats2half2_rn(x, y);
    float2 hf = __half22float2(h);
    __half2 l = __floats2half2_rn(x - hf.x, y - hf.y);
    hi = *reinterpret_cast<uint32_t*>(&h);
    lo = *reinterpret_cast<uint32_t*>(&l);
}

// merge an f16 accumulator pair into 4 floats
__device__ __forceinline__ void merge_h(float* d, const uint32_t* h) {
    float2 a = __half22float2(*reinterpret_cast<const __half2*>(&h[0]));
    float2 b = __half22float2(*reinterpret_cast<const __half2*>(&h[1]));
    d[0] += a.x; d[1] += a.y; d[2] += b.x; d[3] += b.y;
}

// ---------------------------------------------------------------------------
// Elementwise split: fp32 -> fp16 hi + fp16 lo
// ---------------------------------------------------------------------------
__global__ __launch_bounds__(256) void split_kernel(
    const float* __restrict__ in,
    __half* __restrict__ hi, __half* __restrict__ lo)
{
    int i = (blockIdx.x * 256 + threadIdx.x) * 4;
    float4 v = *(const float4*)(in + i);
    uint32_t h0, l0, h1, l1;
    split_pack_f16(v.x, v.y, h0, l0);
    split_pack_f16(v.z, v.w, h1, l1);
    *(uint32_t*)(hi + i)     = h0;
    *(uint32_t*)(hi + i + 2) = h1;
    *(uint32_t*)(lo + i)     = l0;
    *(uint32_t*)(lo + i + 2) = l1;
}

// ---------------------------------------------------------------------------
// Transpose + fp16 split: W[K,N] fp32 -> Wt[N,K] fp16 hi/lo. 32x32 tiles.
// ---------------------------------------------------------------------------
__global__ __launch_bounds__(256) void tsplit_kernel(
    const float* __restrict__ W,
    __half* __restrict__ hi, __half* __restrict__ lo,
    int K, int N)
{
    __shared__ float t[32][33];
    const int n0 = blockIdx.x * 32, k0 = blockIdx.y * 32;
    const int tx = threadIdx.x, ty = threadIdx.y;   // 32 x 8

    #pragma unroll
    for (int j = 0; j < 4; j++)
        t[ty + 8 * j][tx] = W[(size_t)(k0 + ty + 8 * j) * N + n0 + tx];
    __syncthreads();

    #pragma unroll
    for (int j = 0; j < 4; j++) {
        int row = ty + 8 * j;
        float v = t[tx][row];
        __half h = __float2half(v);
        size_t o = (size_t)(n0 + row) * K + k0 + tx;
        hi[o] = h;
        lo[o] = __float2half(v - __half2float(h));
    }
}

// ---------------------------------------------------------------------------
// Transpose + convert (fp16): W[K,N-stride] fp32 -> Wt[n,K]. 32x32 tiles.
// ---------------------------------------------------------------------------
__global__ __launch_bounds__(256) void tconv_f16_kernel(
    const float* __restrict__ W, __half* __restrict__ out, int K, int N)
{
    __shared__ float t[32][33];
    const int n0 = blockIdx.x * 32, k0 = blockIdx.y * 32;
    const int tx = threadIdx.x, ty = threadIdx.y;

    #pragma unroll
    for (int j = 0; j < 4; j++)
        t[ty + 8 * j][tx] = W[(size_t)(k0 + ty + 8 * j) * N + n0 + tx];
    __syncthreads();

    #pragma unroll
    for (int j = 0; j < 4; j++) {
        int row = ty + 8 * j;
        out[(size_t)(n0 + row) * K + k0 + tx] = __float2half(t[tx][row]);
    }
}

// ---------------------------------------------------------------------------
// fp16-split GEMM for Q,K columns: main term f32-accum, cross terms f16-accum.
// 64x128 CTA tile, BK=64, single 48KB buffer, 8 warps 2m x 4n (warp 32x32).
// Outputs fp16 hi/lo split.
// ---------------------------------------------------------------------------
#define GQ_SMEM 49152

__global__ __launch_bounds__(256, 2) void gemm_qk(
    const __half* __restrict__ Ahi, const __half* __restrict__ Alo,
    const __half* __restrict__ Bhi, const __half* __restrict__ Blo,
    __half* __restrict__ Chi, __half* __restrict__ Clo,
    int Mtot, int Ntot, int Ktot)
{
    extern __shared__ char smem[];
    const uint32_t sb = smem_u32(smem);
    const int tid  = threadIdx.x;
    const int wid  = tid >> 5;
    const int lane = tid & 31;
    const int row0 = blockIdx.y * 64, col0 = blockIdx.x * 128;

    const int m0 = (wid & 1) * 32;
    const int n0 = (wid >> 1) * 32;

    const uint32_t sAh = sb;            // 64x128B = 8K
    const uint32_t sAl = sb + 8192;
    const uint32_t sBh = sb + 16384;    // 128x128B = 16K
    const uint32_t sBl = sb + 32768;

    float    acc [2][4][4] = {};
    uint32_t acch[2][4][2] = {};        // f16 accum (zeros)

    const int nchunks = Ktot >> 6;
    for (int c = 0; c < nchunks; c++) {
        #pragma unroll
        for (int i = 0; i < 12; i++) {
            int idx = tid + i * 256;
            if (i < 2) {
                int l = idx;                   // 0..511
                int r = l >> 3, sg = l & 7;
                cp16(sAh + SWZ(r, sg),
                     Ahi + (size_t)(row0 + r) * Ktot + c * 64 + sg * 8);
            } else if (i < 4) {
                int l = idx - 512;
                int r = l >> 3, sg = l & 7;
                cp16(sAl + SWZ(r, sg),
                     Alo + (size_t)(row0 + r) * Ktot + c * 64 + sg * 8);
            } else if (i < 8) {
                int l = idx - 1024;            // 0..1023
                int r = l >> 3, sg = l & 7;
                cp16(sBh + SWZ(r, sg),
                     Bhi + (size_t)(col0 + r) * Ktot + c * 64 + sg * 8);
            } else {
                int l = idx - 2048;
                int r = l >> 3, sg = l & 7;
                cp16(sBl + SWZ(r, sg),
                     Blo + (size_t)(col0 + r) * Ktot + c * 64 + sg * 8);
            }
        }
        CP_WAIT_ALL();
        __syncthreads();

        #pragma unroll
        for (int ks = 0; ks < 4; ks++) {
            uint32_t aH[2][4], aL[2][4];
            #pragma unroll
            for (int mt = 0; mt < 2; mt++) {
                int r   = m0 + mt * 16 + (lane & 15);
                int seg = ks * 2 + (lane >> 4);
                uint32_t off = SWZ(r, seg);
                ldsm_x4(aH[mt], sAh + off);
                ldsm_x4(aL[mt], sAl + off);
            }
            #pragma unroll
            for (int np = 0; np < 2; np++) {
                int nr  = n0 + np * 16 + ((lane >> 4) << 3) + (lane & 7);
                int seg = ks * 2 + ((lane >> 3) & 1);
                uint32_t off = SWZ(nr, seg);
                uint32_t bH[4], bL[4];
                ldsm_x4(bH, sBh + off);
                ldsm_x4(bL, sBl + off);
                #pragma unroll
                for (int mt = 0; mt < 2; mt++) {
                    mma_f16 (acc [mt][np * 2],     aH[mt], bH);
                    mma_f16 (acc [mt][np * 2 + 1], aH[mt], bH + 2);
                    mma_f16h(acch[mt][np * 2],     aH[mt], bL);
                    mma_f16h(acch[mt][np * 2 + 1], aH[mt], bL + 2);
                    mma_f16h(acch[mt][np * 2],     aL[mt], bH);
                    mma_f16h(acch[mt][np * 2 + 1], aL[mt], bH + 2);
                }
            }
        }
        __syncthreads();
    }

    #pragma unroll
    for (int mt = 0; mt < 2; mt++) {
        int r = row0 + m0 + mt * 16 + (lane >> 2);
        #pragma unroll
        for (int nt = 0; nt < 4; nt++) {
            merge_h(acc[mt][nt], acch[mt][nt]);
            int cc = col0 + n0 + nt * 8 + (lane & 3) * 2;
            uint32_t h0, l0, h1, l1;
            split_pack_f16(acc[mt][nt][0], acc[mt][nt][1], h0, l0);
            split_pack_f16(acc[mt][nt][2], acc[mt][nt][3], h1, l1);
            *(uint32_t*)&Chi[(size_t)r * Ntot + cc]       = h0;
            *(uint32_t*)&Clo[(size_t)r * Ntot + cc]       = l0;
            *(uint32_t*)&Chi[(size_t)(r + 8) * Ntot + cc] = h1;
            *(uint32_t*)&Clo[(size_t)(r + 8) * Ntot + cc] = l1;
        }
    }
}

// ---------------------------------------------------------------------------
// Single-term fp16 GEMM (V projection / out projection).
// 64x128 tile, BK=64, single 24KB buffer.
// ---------------------------------------------------------------------------
#define GF_SMEM 24576

__global__ __launch_bounds__(256, 2) void gemm_f16k(
    const __half* __restrict__ A, const __half* __restrict__ Bt,
    float* __restrict__ C, __half* __restrict__ C16,
    int Mtot, int Ntot, int Ktot,
    const float* __restrict__ bias)
{
    extern __shared__ char smem[];
    const uint32_t sb = smem_u32(smem);
    const int tid  = threadIdx.x;
    const int wid  = tid >> 5;
    const int lane = tid & 31;
    const int row0 = blockIdx.y * 64, col0 = blockIdx.x * 128;

    const int m0 = (wid & 1) * 32;
    const int n0 = (wid >> 1) * 32;

    const uint32_t sA = sb;
    const uint32_t sB = sb + 8192;

    float acc[2][4][4] = {};
    const int nchunks = Ktot >> 6;

    for (int c = 0; c < nchunks; c++) {
        #pragma unroll
        for (int i = 0; i < 6; i++) {
            if (i < 2) {
                int local = tid + i * 256;
                int r = local >> 3, seg = local & 7;
                cp16(sA + SWZ(r, seg),
                     A + (size_t)(row0 + r) * Ktot + c * 64 + seg * 8);
            } else {
                int local = tid + (i - 2) * 256;
                int r = local >> 3, seg = local & 7;
                cp16(sB + SWZ(r, seg),
                     Bt + (size_t)(col0 + r) * Ktot + c * 64 + seg * 8);
            }
        }
        CP_WAIT_ALL();
        __syncthreads();

        #pragma unroll
        for (int ks = 0; ks < 4; ks++) {
            uint32_t aH[2][4];
            #pragma unroll
            for (int mt = 0; mt < 2; mt++) {
                int r   = m0 + mt * 16 + (lane & 15);
                int seg = ks * 2 + (lane >> 4);
                ldsm_x4(aH[mt], sA + SWZ(r, seg));
            }
            #pragma unroll
            for (int np = 0; np < 2; np++) {
                int nr  = n0 + np * 16 + ((lane >> 4) << 3) + (lane & 7);
                int seg = ks * 2 + ((lane >> 3) & 1);
                uint32_t bH[4];
                ldsm_x4(bH, sB + SWZ(nr, seg));
                #pragma unroll
                for (int mt = 0; mt < 2; mt++) {
                    mma_f16(acc[mt][np * 2],     aH[mt], bH);
                    mma_f16(acc[mt][np * 2 + 1], aH[mt], bH + 2);
                }
            }
        }
        __syncthreads();
    }

    #pragma unroll
    for (int mt = 0; mt < 2; mt++) {
        int r = row0 + m0 + mt * 16 + (lane >> 2);
        #pragma unroll
        for (int nt = 0; nt < 4; nt++) {
            int cc = col0 + n0 + nt * 8 + (lane & 3) * 2;
            float bx = 0.f, by = 0.f;
            if (bias) { bx = bias[cc]; by = bias[cc + 1]; }
            float v0x = acc[mt][nt][0] + bx, v0y = acc[mt][nt][1] + by;
            float v1x = acc[mt][nt][2] + bx, v1y = acc[mt][nt][3] + by;
            if (C16) {
                *(uint32_t*)&C16[(size_t)r * Ntot + cc]       = pack_f16(v0x, v0y);
                *(uint32_t*)&C16[(size_t)(r + 8) * Ntot + cc] = pack_f16(v1x, v1y);
            } else {
                *(float2*)&C[(size_t)r * Ntot + cc]       = make_float2(v0x, v0y);
                *(float2*)&C[(size_t)(r + 8) * Ntot + cc] = make_float2(v1x, v1y);
            }
        }
    }
}

// ---------------------------------------------------------------------------
// Paired-tile flash attention. QK^T: fp16-split (main f32-accum + cross
// f16-accum). PV: single-term fp16 f32-accum.
// ---------------------------------------------------------------------------
#define AT_SMEM 57344

__global__ __launch_bounds__(128, 2) void attn_mma(
    const __half* __restrict__ qk_hi,
    const __half* __restrict__ qk_lo,
    const __half* __restrict__ v_f16,
    __half* __restrict__ out_f16)
{
    extern __shared__ char smem[];
    const uint32_t sb = smem_u32(smem);
    const uint32_t sQ1h = sb,         sQ1l = sb + 8192;
    const uint32_t sQ2h = sb + 16384, sQ2l = sb + 24576;
    const uint32_t sKh  = sb + 32768, sKl  = sb + 40960;
    const uint32_t sV   = sb + 49152;

    const int tid = threadIdx.x, wid = tid >> 5, lane = tid & 31;
    const int t1 = blockIdx.x;
    const int t2 = (NTILES - 1) - t1;
    const int h  = blockIdx.y;
    const int hoff = h * DHEAD;

    #pragma unroll
    for (int i = 0; i < 4; i++) {
        int idx = tid + i * 128;
        int r = idx >> 3, seg = idx & 7;
        uint32_t off = SWZ(r, seg);
        size_t g1 = (size_t)(t1 * 64 + r) * QK_N + hoff + seg * 8;
        size_t g2 = (size_t)(t2 * 64 + r) * QK_N + hoff + seg * 8;
        cp16(sQ1h + off, qk_hi + g1);
        cp16(sQ1l + off, qk_lo + g1);
        cp16(sQ2h + off, qk_hi + g2);
        cp16(sQ2l + off, qk_lo + g2);
    }

    float o1[8][4] = {}, o2[8][4] = {};
    float m1[2] = {-1e30f, -1e30f}, l1[2] = {0.f, 0.f};
    float m2[2] = {-1e30f, -1e30f}, l2[2] = {0.f, 0.f};

    const int rloc = wid * 16 + (lane >> 2);
    const int rA1 = t1 * 64 + rloc;
    const int rA2 = t2 * 64 + rloc;

    auto process = [&](uint32_t sQh, uint32_t sQl, float (*o)[4],
                       float* m_i, float* l_i, int rA, bool maskit, int k0) {
        // S = Q K^T : main f32-accum + cross f16-accum
        float    s [8][4] = {};
        uint32_t shh[8][2] = {};
        #pragma unroll
        for (int ks = 0; ks < 4; ks++) {
            uint32_t aH[4], aL[4];
            {
                int r   = wid * 16 + (lane & 15);
                int seg = ks * 2 + (lane >> 4);
                ldsm_x4(aH, sQh + SWZ(r, seg));
                ldsm_x4(aL, sQl + SWZ(r, seg));
            }
            #pragma unroll
            for (int np = 0; np < 4; np++) {
                int nr = np * 16 + ((lane >> 4) << 3) + (lane & 7);
                int sg = ks * 2 + ((lane >> 3) & 1);
                uint32_t off = SWZ(nr, sg);
                uint32_t bH[4], bL[4];
                ldsm_x4(bH, sKh + off);
                ldsm_x4(bL, sKl + off);
                mma_f16 (s  [np * 2],     aH, bH);
                mma_f16 (s  [np * 2 + 1], aH, bH + 2);
                mma_f16h(shh[np * 2],     aH, bL);
                mma_f16h(shh[np * 2 + 1], aH, bL + 2);
                mma_f16h(shh[np * 2],     aL, bH);
                mma_f16h(shh[np * 2 + 1], aL, bH + 2);
            }
        }
        #pragma unroll
        for (int j = 0; j < 8; j++) merge_h(s[j], shh[j]);

        // scale + causal mask
        #pragma unroll
        for (int j = 0; j < 8; j++) {
            s[j][0] *= 0.125f; s[j][1] *= 0.125f;
            s[j][2] *= 0.125f; s[j][3] *= 0.125f;
        }
        if (maskit) {
            #pragma unroll
            for (int j = 0; j < 8; j++) {
                int col = k0 + j * 8 + (lane & 3) * 2;
                if (col > rA)         s[j][0] = -1e30f;
                if (col + 1 > rA)     s[j][1] = -1e30f;
                if (col > rA + 8)     s[j][2] = -1e30f;
                if (col + 1 > rA + 8) s[j][3] = -1e30f;
            }
        }

        // online softmax on fragments
        float mxA = -1e30f, mxB = -1e30f;
        #pragma unroll
        for (int j = 0; j < 8; j++) {
            mxA = fmaxf(mxA, fmaxf(s[j][0], s[j][1]));
            mxB = fmaxf(mxB, fmaxf(s[j][2], s[j][3]));
        }
        mxA = fmaxf(mxA, __shfl_xor_sync(0xffffffffu, mxA, 1));
        mxA = fmaxf(mxA, __shfl_xor_sync(0xffffffffu, mxA, 2));
        mxB = fmaxf(mxB, __shfl_xor_sync(0xffffffffu, mxB, 1));
        mxB = fmaxf(mxB, __shfl_xor_sync(0xffffffffu, mxB, 2));

        float mA = fmaxf(m_i[0], mxA), mB = fmaxf(m_i[1], mxB);
        float scA = __expf(m_i[0] - mA), scB = __expf(m_i[1] - mB);
        float lA = 0.f, lB = 0.f;
        #pragma unroll
        for (int j = 0; j < 8; j++) {
            s[j][0] = __expf(s[j][0] - mA);
            s[j][1] = __expf(s[j][1] - mA);
            s[j][2] = __expf(s[j][2] - mB);
            s[j][3] = __expf(s[j][3] - mB);
            lA += s[j][0] + s[j][1];
            lB += s[j][2] + s[j][3];
        }
        lA += __shfl_xor_sync(0xffffffffu, lA, 1);
        lA += __shfl_xor_sync(0xffffffffu, lA, 2);
        lB += __shfl_xor_sync(0xffffffffu, lB, 1);
        lB += __shfl_xor_sync(0xffffffffu, lB, 2);
        l_i[0] = l_i[0] * scA + lA;  m_i[0] = mA;
        l_i[1] = l_i[1] * scB + lB;  m_i[1] = mB;
        #pragma unroll
        for (int j = 0; j < 8; j++) {
            o[j][0] *= scA; o[j][1] *= scA;
            o[j][2] *= scB; o[j][3] *= scB;
        }

        // O += P V  (single-term fp16, f32 accum)
        #pragma unroll
        for (int t = 0; t < 4; t++) {
            uint32_t pH[4];
            pH[0] = pack_f16(s[2 * t][0],     s[2 * t][1]);
            pH[1] = pack_f16(s[2 * t][2],     s[2 * t][3]);
            pH[2] = pack_f16(s[2 * t + 1][0], s[2 * t + 1][1]);
            pH[3] = pack_f16(s[2 * t + 1][2], s[2 * t + 1][3]);
            #pragma unroll
            for (int sp = 0; sp < 4; sp++) {
                int g  = lane >> 3, rr = lane & 7;
                uint32_t off = SWZ(t * 16 + rr + ((g & 1) << 3),
                                   sp * 2 + (g >> 1));
                uint32_t bH[4];
                ldsm_x4_t(bH, sV + off);
                mma_f16(o[sp * 2],     pH, bH);
                mma_f16(o[sp * 2 + 1], pH, bH + 2);
            }
        }
    };

    for (int kt = 0; kt <= t2; kt++) {
        const int k0 = kt * 64;

        #pragma unroll
        for (int i = 0; i < 4; i++) {
            int idx = tid + i * 128;
            int r = idx >> 3, seg = idx & 7;
            uint32_t off = SWZ(r, seg);
            size_t gk = (size_t)(k0 + r) * QK_N + DIM + hoff + seg * 8;
            cp16(sKh + off, qk_hi + gk);
            cp16(sKl + off, qk_lo + gk);
            cp16(sV + off, v_f16 + (size_t)(k0 + r) * DIM + hoff + seg * 8);
        }
        CP_WAIT_ALL();
        __syncthreads();

        process(sQ2h, sQ2l, o2, m2, l2, rA2, kt == t2, k0);
        if (kt <= t1)
            process(sQ1h, sQ1l, o1, m1, l1, rA1, kt == t1, k0);

        __syncthreads();
    }

    // epilogue: normalize, write fp16
    {
        float invA = 1.0f / l2[0], invB = 1.0f / l2[1];
        #pragma unroll
        for (int j = 0; j < 8; j++) {
            int d = hoff + j * 8 + (lane & 3) * 2;
            *(uint32_t*)&out_f16[(size_t)rA2 * DIM + d] =
                pack_f16(o2[j][0] * invA, o2[j][1] * invA);
            *(uint32_t*)&out_f16[(size_t)(rA2 + 8) * DIM + d] =
                pack_f16(o2[j][2] * invB, o2[j][3] * invB);
        }
    }
    {
        float invA = 1.0f / l1[0], invB = 1.0f / l1[1];
        #pragma unroll
        for (int j = 0; j < 8; j++) {
            int d = hoff + j * 8 + (lane & 3) * 2;
            *(uint32_t*)&out_f16[(size_t)rA1 * DIM + d] =
                pack_f16(o1[j][0] * invA, o1[j][1] * invA);
            *(uint32_t*)&out_f16[(size_t)(rA1 + 8) * DIM + d] =
                pack_f16(o1[j][2] * invB, o1[j][3] * invB);
        }
    }
}

// ---------------------------------------------------------------------------
extern "C" void kernel_launch(void* const* d_in, const int* in_sizes, int n_in,
                              void* d_out, int out_size)
{
    const float* x    = (const float*)d_in[0];
    const float* Wqkv = (const float*)d_in[1];
    const float* Wout = (const float*)d_in[2];
    const float* bias = (const float*)d_in[3];
    float* out = (float*)d_out;

    __half *xh, *xl, *wqh, *wql, *wvt, *qh, *ql, *vf, *wof, *af;
    cudaGetSymbolAddress((void**)&xh,  g_x_hi);
    cudaGetSymbolAddress((void**)&xl,  g_x_lo);
    cudaGetSymbolAddress((void**)&wqh, g_wqk_hi);
    cudaGetSymbolAddress((void**)&wql, g_wqk_lo);
    cudaGetSymbolAddress((void**)&wvt, g_wvt_f16);
    cudaGetSymbolAddress((void**)&qh,  g_qk_hi);
    cudaGetSymbolAddress((void**)&ql,  g_qk_lo);
    cudaGetSymbolAddress((void**)&vf,  g_v_f16);
    cudaGetSymbolAddress((void**)&wof, g_wout_f16);
    cudaGetSymbolAddress((void**)&af,  g_attn_f16);

    cudaFuncSetAttribute(gemm_qk, cudaFuncAttributeMaxDynamicSharedMemorySize,
                         GQ_SMEM);
    cudaFuncSetAttribute(gemm_f16k, cudaFuncAttributeMaxDynamicSharedMemorySize,
                         GF_SMEM);
    cudaFuncSetAttribute(attn_mma, cudaFuncAttributeMaxDynamicSharedMemorySize,
                         AT_SMEM);

    // Prep
    split_kernel<<<SEQ * DIM / 1024, 256>>>(x, xh, xl);
    tsplit_kernel<<<dim3(QK_N / 32, DIM / 32), dim3(32, 8)>>>(Wqkv, wqh, wql,
                                                              DIM, QKV_N);
    tconv_f16_kernel<<<dim3(DIM / 32, DIM / 32), dim3(32, 8)>>>(Wqkv + QK_N,
                                                                wvt, DIM, QKV_N);
    tconv_f16_kernel<<<dim3(DIM / 32, DIM / 32), dim3(32, 8)>>>(Wout, wof,
                                                                DIM, DIM);

    // 1a) Q,K = x @ Wqkv[:, :2048]  (fp16-split; main f32 + cross f16 accum)
    gemm_qk<<<dim3(QK_N / 128, SEQ / 64), 256, GQ_SMEM>>>(
        xh, xl, wqh, wql, qh, ql, SEQ, QK_N, DIM);

    // 1b) V = x @ Wqkv[:, 2048:]  (single fp16; A = fp16 hi part of x)
    gemm_f16k<<<dim3(DIM / 128, SEQ / 64), 256, GF_SMEM>>>(
        xh, wvt, nullptr, vf, SEQ, DIM, DIM, nullptr);

    // 2) attention (paired tiles) -> fp16
    attn_mma<<<dim3(NTILES / 2, NHEAD), 128, AT_SMEM>>>(qh, ql, vf, af);

    // 3) out = attn @ Wout + bias
    gemm_f16k<<<dim3(DIM / 128, SEQ / 64), 256, GF_SMEM>>>(
        af, wof, out, nullptr, SEQ, DIM, DIM, bias);
}

// round 16
// speedup vs baseline: 1.6897x; 1.2309x over previous
#include <cuda_runtime.h>
#include <cuda_bf16.h>
#include <cuda_fp16.h>
#include <cstdint>

#define SEQ 2048
#define DIM 1024
#define NHEAD 16
#define DHEAD 64
#define QKV_N (3 * DIM)   // 3072
#define QK_N (2 * DIM)    // 2048
#define NTILES (SEQ / 64) // 32

// ---------------------------------------------------------------------------
// Scratch (device globals — allocation-free rule)
// ---------------------------------------------------------------------------
__device__ __half g_x_hi[SEQ * DIM];      // fp16(x)
__device__ __half g_x_lo[SEQ * DIM];      // fp16 residual
__device__ __half g_wqk_f16[QK_N * DIM];  // [N,K] transposed, QK cols (hi only)
__device__ __half g_wvt_f16[DIM * DIM];   // [N,K] transposed, V cols
__device__ __half g_qk_hi[SEQ * QK_N];    // Q,K fp16 hi
__device__ __half g_qk_lo[SEQ * QK_N];    // Q,K fp16 lo (used for Q)
__device__ __half g_v_f16[SEQ * DIM];     // V fp16
__device__ __half g_wout_f16[DIM * DIM];  // [N,K] transposed
__device__ __half g_attn_f16[SEQ * DIM];  // attention output

// ---------------------------------------------------------------------------
// PTX helpers
// ---------------------------------------------------------------------------
__device__ __forceinline__ uint32_t smem_u32(const void* p) {
    uint32_t a;
    asm("{ .reg .u64 t; cvta.to.shared.u64 t, %1; cvt.u32.u64 %0, t; }"
        : "=r"(a) : "l"(p));
    return a;
}

__device__ __forceinline__ void ldsm_x4(uint32_t* r, uint32_t addr) {
    asm volatile("ldmatrix.sync.aligned.m8n8.x4.shared.b16 {%0,%1,%2,%3}, [%4];"
                 : "=r"(r[0]), "=r"(r[1]), "=r"(r[2]), "=r"(r[3]) : "r"(addr));
}

__device__ __forceinline__ void ldsm_x4_t(uint32_t* r, uint32_t addr) {
    asm volatile("ldmatrix.sync.aligned.m8n8.x4.trans.shared.b16 {%0,%1,%2,%3}, [%4];"
                 : "=r"(r[0]), "=r"(r[1]), "=r"(r[2]), "=r"(r[3]) : "r"(addr));
}

// fp16 inputs, fp32 accumulator
__device__ __forceinline__ void mma_f16(float* d, const uint32_t* a,
                                        const uint32_t* b) {
    asm("mma.sync.aligned.m16n8k16.row.col.f32.f16.f16.f32 "
        "{%0,%1,%2,%3}, {%4,%5,%6,%7}, {%8,%9}, {%0,%1,%2,%3};"
        : "+f"(d[0]), "+f"(d[1]), "+f"(d[2]), "+f"(d[3])
        : "r"(a[0]), "r"(a[1]), "r"(a[2]), "r"(a[3]), "r"(b[0]), "r"(b[1]));
}

__device__ __forceinline__ void cp16(uint32_t dst, const void* src) {
    asm volatile("cp.async.cg.shared.global [%0], [%1], 16;"
                 :: "r"(dst), "l"(src));
}
#define CP_WAIT_ALL() asm volatile("cp.async.wait_all;" ::: "memory")

// swizzled smem byte offset for (row, 16B-seg), 128B rows (8 segs)
#define SWZ(r, seg) ((uint32_t)((r) * 128 + (((seg) ^ ((r) & 7)) << 4)))

__device__ __forceinline__ uint32_t pack_f16(float x, float y) {
    __half2 h = __floats2half2_rn(x, y);
    return *reinterpret_cast<uint32_t*>(&h);
}

// pack 2 floats into fp16 hi + fp16 residual lo
__device__ __forceinline__ void split_pack_f16(float x, float y,
                                               uint32_t& hi, uint32_t& lo) {
    __half2 h = __floats2half2_rn(x, y);
    float2 hf = __half22float2(h);
    __half2 l = __floats2half2_rn(x - hf.x, y - hf.y);
    hi = *reinterpret_cast<uint32_t*>(&h);
    lo = *reinterpret_cast<uint32_t*>(&l);
}

// ---------------------------------------------------------------------------
// Elementwise split: fp32 -> fp16 hi + fp16 lo
// ---------------------------------------------------------------------------
__global__ __launch_bounds__(256) void split_kernel(
    const float* __restrict__ in,
    __half* __restrict__ hi, __half* __restrict__ lo)
{
    int i = (blockIdx.x * 256 + threadIdx.x) * 4;
    float4 v = *(const float4*)(in + i);
    uint32_t h0, l0, h1, l1;
    split_pack_f16(v.x, v.y, h0, l0);
    split_pack_f16(v.z, v.w, h1, l1);
    *(uint32_t*)(hi + i)     = h0;
    *(uint32_t*)(hi + i + 2) = h1;
    *(uint32_t*)(lo + i)     = l0;
    *(uint32_t*)(lo + i + 2) = l1;
}

// ---------------------------------------------------------------------------
// Unified weight prep: all three weight blocks are transpose + fp16 convert.
// grid = (128, 32): bx<64 -> Wqkv QK cols; bx<96 -> Wqkv V cols; else Wout.
// ---------------------------------------------------------------------------
__global__ __launch_bounds__(256) void wprep_kernel(
    const float* __restrict__ Wqkv, const float* __restrict__ Wout,
    __half* __restrict__ wqk, __half* __restrict__ wvt,
    __half* __restrict__ wof)
{
    __shared__ float t[32][33];
    const int bx = blockIdx.x, k0 = blockIdx.y * 32;
    const int tx = threadIdx.x, ty = threadIdx.y;   // 32 x 8

    const float* src; int srcN, n0; __half* dst;
    if (bx < 64)      { src = Wqkv;        srcN = QKV_N; n0 = bx * 32;        dst = wqk; }
    else if (bx < 96) { src = Wqkv + QK_N; srcN = QKV_N; n0 = (bx - 64) * 32; dst = wvt; }
    else              { src = Wout;        srcN = DIM;   n0 = (bx - 96) * 32; dst = wof; }

    #pragma unroll
    for (int j = 0; j < 4; j++)
        t[ty + 8 * j][tx] = src[(size_t)(k0 + ty + 8 * j) * srcN + n0 + tx];
    __syncthreads();

    #pragma unroll
    for (int j = 0; j < 4; j++) {
        int row = ty + 8 * j;
        dst[(size_t)(n0 + row) * DIM + k0 + tx] = __float2half(t[tx][row]);
    }
}

// ---------------------------------------------------------------------------
// 2-term QK GEMM: Q,K = (xhi + xlo) @ Whi^T.  (W residual dropped.)
// 64x128 CTA tile, BK=64, single 32KB buffer, 8 warps 2m x 4n (warp 32x32).
// Outputs fp16 hi/lo split.
// ---------------------------------------------------------------------------
#define GQ_SMEM 32768

__global__ __launch_bounds__(256, 2) void gemm_qk(
    const __half* __restrict__ Ahi, const __half* __restrict__ Alo,
    const __half* __restrict__ Bh,
    __half* __restrict__ Chi, __half* __restrict__ Clo,
    int Mtot, int Ntot, int Ktot)
{
    extern __shared__ char smem[];
    const uint32_t sb = smem_u32(smem);
    const int tid  = threadIdx.x;
    const int wid  = tid >> 5;
    const int lane = tid & 31;
    const int row0 = blockIdx.y * 64, col0 = blockIdx.x * 128;

    const int m0 = (wid & 1) * 32;
    const int n0 = (wid >> 1) * 32;

    const uint32_t sAh = sb;            // 64x128B = 8K
    const uint32_t sAl = sb + 8192;
    const uint32_t sBh = sb + 16384;    // 128x128B = 16K

    float acc[2][4][4] = {};

    const int nchunks = Ktot >> 6;
    for (int c = 0; c < nchunks; c++) {
        #pragma unroll
        for (int i = 0; i < 8; i++) {
            int idx = tid + i * 256;
            if (i < 2) {
                int l = idx;                   // 0..511
                int r = l >> 3, sg = l & 7;
                cp16(sAh + SWZ(r, sg),
                     Ahi + (size_t)(row0 + r) * Ktot + c * 64 + sg * 8);
            } else if (i < 4) {
                int l = idx - 512;
                int r = l >> 3, sg = l & 7;
                cp16(sAl + SWZ(r, sg),
                     Alo + (size_t)(row0 + r) * Ktot + c * 64 + sg * 8);
            } else {
                int l = idx - 1024;            // 0..1023
                int r = l >> 3, sg = l & 7;
                cp16(sBh + SWZ(r, sg),
                     Bh + (size_t)(col0 + r) * Ktot + c * 64 + sg * 8);
            }
        }
        CP_WAIT_ALL();
        __syncthreads();

        #pragma unroll
        for (int ks = 0; ks < 4; ks++) {
            uint32_t aH[2][4], aL[2][4];
            #pragma unroll
            for (int mt = 0; mt < 2; mt++) {
                int r   = m0 + mt * 16 + (lane & 15);
                int seg = ks * 2 + (lane >> 4);
                uint32_t off = SWZ(r, seg);
                ldsm_x4(aH[mt], sAh + off);
                ldsm_x4(aL[mt], sAl + off);
            }
            #pragma unroll
            for (int np = 0; np < 2; np++) {
                int nr  = n0 + np * 16 + ((lane >> 4) << 3) + (lane & 7);
                int seg = ks * 2 + ((lane >> 3) & 1);
                uint32_t bH[4];
                ldsm_x4(bH, sBh + SWZ(nr, seg));
                #pragma unroll
                for (int mt = 0; mt < 2; mt++) {
                    mma_f16(acc[mt][np * 2],     aH[mt], bH);
                    mma_f16(acc[mt][np * 2 + 1], aH[mt], bH + 2);
                    mma_f16(acc[mt][np * 2],     aL[mt], bH);
                    mma_f16(acc[mt][np * 2 + 1], aL[mt], bH + 2);
                }
            }
        }
        __syncthreads();
    }

    #pragma unroll
    for (int mt = 0; mt < 2; mt++) {
        int r = row0 + m0 + mt * 16 + (lane >> 2);
        #pragma unroll
        for (int nt = 0; nt < 4; nt++) {
            int cc = col0 + n0 + nt * 8 + (lane & 3) * 2;
            uint32_t h0, l0, h1, l1;
            split_pack_f16(acc[mt][nt][0], acc[mt][nt][1], h0, l0);
            split_pack_f16(acc[mt][nt][2], acc[mt][nt][3], h1, l1);
            *(uint32_t*)&Chi[(size_t)r * Ntot + cc]       = h0;
            *(uint32_t*)&Clo[(size_t)r * Ntot + cc]       = l0;
            *(uint32_t*)&Chi[(size_t)(r + 8) * Ntot + cc] = h1;
            *(uint32_t*)&Clo[(size_t)(r + 8) * Ntot + cc] = l1;
        }
    }
}

// ---------------------------------------------------------------------------
// Single-term fp16 GEMM (V projection / out projection).
// 64x128 tile, BK=64, single 24KB buffer.
// ---------------------------------------------------------------------------
#define GF_SMEM 24576

__global__ __launch_bounds__(256, 2) void gemm_f16k(
    const __half* __restrict__ A, const __half* __restrict__ Bt,
    float* __restrict__ C, __half* __restrict__ C16,
    int Mtot, int Ntot, int Ktot,
    const float* __restrict__ bias)
{
    extern __shared__ char smem[];
    const uint32_t sb = smem_u32(smem);
    const int tid  = threadIdx.x;
    const int wid  = tid >> 5;
    const int lane = tid & 31;
    const int row0 = blockIdx.y * 64, col0 = blockIdx.x * 128;

    const int m0 = (wid & 1) * 32;
    const int n0 = (wid >> 1) * 32;

    const uint32_t sA = sb;
    const uint32_t sB = sb + 8192;

    float acc[2][4][4] = {};
    const int nchunks = Ktot >> 6;

    for (int c = 0; c < nchunks; c++) {
        #pragma unroll
        for (int i = 0; i < 6; i++) {
            if (i < 2) {
                int local = tid + i * 256;
                int r = local >> 3, seg = local & 7;
                cp16(sA + SWZ(r, seg),
                     A + (size_t)(row0 + r) * Ktot + c * 64 + seg * 8);
            } else {
                int local = tid + (i - 2) * 256;
                int r = local >> 3, seg = local & 7;
                cp16(sB + SWZ(r, seg),
                     Bt + (size_t)(col0 + r) * Ktot + c * 64 + seg * 8);
            }
        }
        CP_WAIT_ALL();
        __syncthreads();

        #pragma unroll
        for (int ks = 0; ks < 4; ks++) {
            uint32_t aH[2][4];
            #pragma unroll
            for (int mt = 0; mt < 2; mt++) {
                int r   = m0 + mt * 16 + (lane & 15);
                int seg = ks * 2 + (lane >> 4);
                ldsm_x4(aH[mt], sA + SWZ(r, seg));
            }
            #pragma unroll
            for (int np = 0; np < 2; np++) {
                int nr  = n0 + np * 16 + ((lane >> 4) << 3) + (lane & 7);
                int seg = ks * 2 + ((lane >> 3) & 1);
                uint32_t bH[4];
                ldsm_x4(bH, sB + SWZ(nr, seg));
                #pragma unroll
                for (int mt = 0; mt < 2; mt++) {
                    mma_f16(acc[mt][np * 2],     aH[mt], bH);
                    mma_f16(acc[mt][np * 2 + 1], aH[mt], bH + 2);
                }
            }
        }
        __syncthreads();
    }

    #pragma unroll
    for (int mt = 0; mt < 2; mt++) {
        int r = row0 + m0 + mt * 16 + (lane >> 2);
        #pragma unroll
        for (int nt = 0; nt < 4; nt++) {
            int cc = col0 + n0 + nt * 8 + (lane & 3) * 2;
            float bx = 0.f, by = 0.f;
            if (bias) { bx = bias[cc]; by = bias[cc + 1]; }
            float v0x = acc[mt][nt][0] + bx, v0y = acc[mt][nt][1] + by;
            float v1x = acc[mt][nt][2] + bx, v1y = acc[mt][nt][3] + by;
            if (C16) {
                *(uint32_t*)&C16[(size_t)r * Ntot + cc]       = pack_f16(v0x, v0y);
                *(uint32_t*)&C16[(size_t)(r + 8) * Ntot + cc] = pack_f16(v1x, v1y);
            } else {
                *(float2*)&C[(size_t)r * Ntot + cc]       = make_float2(v0x, v0y);
                *(float2*)&C[(size_t)(r + 8) * Ntot + cc] = make_float2(v1x, v1y);
            }
        }
    }
}

// ---------------------------------------------------------------------------
// Paired-tile flash attention. QK^T: 2-term (Qhi+Qlo)·Khi^T, f32 accum.
// PV: single-term fp16 f32-accum. smem 48KB -> 3 CTAs/SM.
// ---------------------------------------------------------------------------
#define AT_SMEM 49152

__global__ __launch_bounds__(128, 3) void attn_mma(
    const __half* __restrict__ qk_hi,
    const __half* __restrict__ qk_lo,
    const __half* __restrict__ v_f16,
    __half* __restrict__ out_f16)
{
    extern __shared__ char smem[];
    const uint32_t sb = smem_u32(smem);
    const uint32_t sQ1h = sb,         sQ1l = sb + 8192;
    const uint32_t sQ2h = sb + 16384, sQ2l = sb + 24576;
    const uint32_t sKh  = sb + 32768;
    const uint32_t sV   = sb + 40960;

    const int tid = threadIdx.x, wid = tid >> 5, lane = tid & 31;
    const int t1 = blockIdx.x;
    const int t2 = (NTILES - 1) - t1;
    const int h  = blockIdx.y;
    const int hoff = h * DHEAD;

    #pragma unroll
    for (int i = 0; i < 4; i++) {
        int idx = tid + i * 128;
        int r = idx >> 3, seg = idx & 7;
        uint32_t off = SWZ(r, seg);
        size_t g1 = (size_t)(t1 * 64 + r) * QK_N + hoff + seg * 8;
        size_t g2 = (size_t)(t2 * 64 + r) * QK_N + hoff + seg * 8;
        cp16(sQ1h + off, qk_hi + g1);
        cp16(sQ1l + off, qk_lo + g1);
        cp16(sQ2h + off, qk_hi + g2);
        cp16(sQ2l + off, qk_lo + g2);
    }

    float o1[8][4] = {}, o2[8][4] = {};
    float m1[2] = {-1e30f, -1e30f}, l1[2] = {0.f, 0.f};
    float m2[2] = {-1e30f, -1e30f}, l2[2] = {0.f, 0.f};

    const int rloc = wid * 16 + (lane >> 2);
    const int rA1 = t1 * 64 + rloc;
    const int rA2 = t2 * 64 + rloc;

    auto process = [&](uint32_t sQh, uint32_t sQl, float (*o)[4],
                       float* m_i, float* l_i, int rA, bool maskit, int k0) {
        // S = (Qhi + Qlo) Khi^T, f32 accum
        float s[8][4] = {};
        #pragma unroll
        for (int ks = 0; ks < 4; ks++) {
            uint32_t aH[4], aL[4];
            {
                int r   = wid * 16 + (lane & 15);
                int seg = ks * 2 + (lane >> 4);
                ldsm_x4(aH, sQh + SWZ(r, seg));
                ldsm_x4(aL, sQl + SWZ(r, seg));
            }
            #pragma unroll
            for (int np = 0; np < 4; np++) {
                int nr = np * 16 + ((lane >> 4) << 3) + (lane & 7);
                int sg = ks * 2 + ((lane >> 3) & 1);
                uint32_t bH[4];
                ldsm_x4(bH, sKh + SWZ(nr, sg));
                mma_f16(s[np * 2],     aH, bH);
                mma_f16(s[np * 2 + 1], aH, bH + 2);
                mma_f16(s[np * 2],     aL, bH);
                mma_f16(s[np * 2 + 1], aL, bH + 2);
            }
        }

        // scale + causal mask
        #pragma unroll
        for (int j = 0; j < 8; j++) {
            s[j][0] *= 0.125f; s[j][1] *= 0.125f;
            s[j][2] *= 0.125f; s[j][3] *= 0.125f;
        }
        if (maskit) {
            #pragma unroll
            for (int j = 0; j < 8; j++) {
                int col = k0 + j * 8 + (lane & 3) * 2;
                if (col > rA)         s[j][0] = -1e30f;
                if (col + 1 > rA)     s[j][1] = -1e30f;
                if (col > rA + 8)     s[j][2] = -1e30f;
                if (col + 1 > rA + 8) s[j][3] = -1e30f;
            }
        }

        // online softmax on fragments
        float mxA = -1e30f, mxB = -1e30f;
        #pragma unroll
        for (int j = 0; j < 8; j++) {
            mxA = fmaxf(mxA, fmaxf(s[j][0], s[j][1]));
            mxB = fmaxf(mxB, fmaxf(s[j][2], s[j][3]));
        }
        mxA = fmaxf(mxA, __shfl_xor_sync(0xffffffffu, mxA, 1));
        mxA = fmaxf(mxA, __shfl_xor_sync(0xffffffffu, mxA, 2));
        mxB = fmaxf(mxB, __shfl_xor_sync(0xffffffffu, mxB, 1));
        mxB = fmaxf(mxB, __shfl_xor_sync(0xffffffffu, mxB, 2));

        float mA = fmaxf(m_i[0], mxA), mB = fmaxf(m_i[1], mxB);
        float scA = __expf(m_i[0] - mA), scB = __expf(m_i[1] - mB);
        float lA = 0.f, lB = 0.f;
        #pragma unroll
        for (int j = 0; j < 8; j++) {
            s[j][0] = __expf(s[j][0] - mA);
            s[j][1] = __expf(s[j][1] - mA);
            s[j][2] = __expf(s[j][2] - mB);
            s[j][3] = __expf(s[j][3] - mB);
            lA += s[j][0] + s[j][1];
            lB += s[j][2] + s[j][3];
        }
        lA += __shfl_xor_sync(0xffffffffu, lA, 1);
        lA += __shfl_xor_sync(0xffffffffu, lA, 2);
        lB += __shfl_xor_sync(0xffffffffu, lB, 1);
        lB += __shfl_xor_sync(0xffffffffu, lB, 2);
        l_i[0] = l_i[0] * scA + lA;  m_i[0] = mA;
        l_i[1] = l_i[1] * scB + lB;  m_i[1] = mB;
        #pragma unroll
        for (int j = 0; j < 8; j++) {
            o[j][0] *= scA; o[j][1] *= scA;
            o[j][2] *= scB; o[j][3] *= scB;
        }

        // O += P V  (single-term fp16, f32 accum)
        #pragma unroll
        for (int t = 0; t < 4; t++) {
            uint32_t pH[4];
            pH[0] = pack_f16(s[2 * t][0],     s[2 * t][1]);
            pH[1] = pack_f16(s[2 * t][2],     s[2 * t][3]);
            pH[2] = pack_f16(s[2 * t + 1][0], s[2 * t + 1][1]);
            pH[3] = pack_f16(s[2 * t + 1][2], s[2 * t + 1][3]);
            #pragma unroll
            for (int sp = 0; sp < 4; sp++) {
                int g  = lane >> 3, rr = lane & 7;
                uint32_t off = SWZ(t * 16 + rr + ((g & 1) << 3),
                                   sp * 2 + (g >> 1));
                uint32_t bH[4];
                ldsm_x4_t(bH, sV + off);
                mma_f16(o[sp * 2],     pH, bH);
                mma_f16(o[sp * 2 + 1], pH, bH + 2);
            }
        }
    };

    for (int kt = 0; kt <= t2; kt++) {
        const int k0 = kt * 64;

        #pragma unroll
        for (int i = 0; i < 4; i++) {
            int idx = tid + i * 128;
            int r = idx >> 3, seg = idx & 7;
            uint32_t off = SWZ(r, seg);
            size_t gk = (size_t)(k0 + r) * QK_N + DIM + hoff + seg * 8;
            cp16(sKh + off, qk_hi + gk);
            cp16(sV + off, v_f16 + (size_t)(k0 + r) * DIM + hoff + seg * 8);
        }
        CP_WAIT_ALL();
        __syncthreads();

        process(sQ2h, sQ2l, o2, m2, l2, rA2, kt == t2, k0);
        if (kt <= t1)
            process(sQ1h, sQ1l, o1, m1, l1, rA1, kt == t1, k0);

        __syncthreads();
    }

    // epilogue: normalize, write fp16
    {
        float invA = 1.0f / l2[0], invB = 1.0f / l2[1];
        #pragma unroll
        for (int j = 0; j < 8; j++) {
            int d = hoff + j * 8 + (lane & 3) * 2;
            *(uint32_t*)&out_f16[(size_t)rA2 * DIM + d] =
                pack_f16(o2[j][0] * invA, o2[j][1] * invA);
            *(uint32_t*)&out_f16[(size_t)(rA2 + 8) * DIM + d] =
                pack_f16(o2[j][2] * invB, o2[j][3] * invB);
        }
    }
    {
        float invA = 1.0f / l1[0], invB = 1.0f / l1[1];
        #pragma unroll
        for (int j = 0; j < 8; j++) {
            int d = hoff + j * 8 + (lane & 3) * 2;
            *(uint32_t*)&out_f16[(size_t)rA1 * DIM + d] =
                pack_f16(o1[j][0] * invA, o1[j][1] * invA);
            *(uint32_t*)&out_f16[(size_t)(rA1 + 8) * DIM + d] =
                pack_f16(o1[j][2] * invB, o1[j][3] * invB);
        }
    }
}

// ---------------------------------------------------------------------------
extern "C" void kernel_launch(void* const* d_in, const int* in_sizes, int n_in,
                              void* d_out, int out_size)
{
    const float* x    = (const float*)d_in[0];
    const float* Wqkv = (const float*)d_in[1];
    const float* Wout = (const float*)d_in[2];
    const float* bias = (const float*)d_in[3];
    float* out = (float*)d_out;

    __half *xh, *xl, *wqk, *wvt, *qh, *ql, *vf, *wof, *af;
    cudaGetSymbolAddress((void**)&xh,  g_x_hi);
    cudaGetSymbolAddress((void**)&xl,  g_x_lo);
    cudaGetSymbolAddress((void**)&wqk, g_wqk_f16);
    cudaGetSymbolAddress((void**)&wvt, g_wvt_f16);
    cudaGetSymbolAddress((void**)&qh,  g_qk_hi);
    cudaGetSymbolAddress((void**)&ql,  g_qk_lo);
    cudaGetSymbolAddress((void**)&vf,  g_v_f16);
    cudaGetSymbolAddress((void**)&wof, g_wout_f16);
    cudaGetSymbolAddress((void**)&af,  g_attn_f16);

    cudaFuncSetAttribute(gemm_qk, cudaFuncAttributeMaxDynamicSharedMemorySize,
                         GQ_SMEM);
    cudaFuncSetAttribute(gemm_f16k, cudaFuncAttributeMaxDynamicSharedMemorySize,
                         GF_SMEM);
    cudaFuncSetAttribute(attn_mma, cudaFuncAttributeMaxDynamicSharedMemorySize,
                         AT_SMEM);

    // Prep: split x + unified weight transpose/convert
    split_kernel<<<SEQ * DIM / 1024, 256>>>(x, xh, xl);
    wprep_kernel<<<dim3(128, 32), dim3(32, 8)>>>(Wqkv, Wout, wqk, wvt, wof);

    // 1a) Q,K = (xhi + xlo) @ Wqk_hi^T  (2-term, fp16 split out)
    gemm_qk<<<dim3(QK_N / 128, SEQ / 64), 256, GQ_SMEM>>>(
        xh, xl, wqk, qh, ql, SEQ, QK_N, DIM);

    // 1b) V = xhi @ Wv^T  (single fp16)
    gemm_f16k<<<dim3(DIM / 128, SEQ / 64), 256, GF_SMEM>>>(
        xh, wvt, nullptr, vf, SEQ, DIM, DIM, nullptr);

    // 2) attention (paired tiles, 2-term QK^T) -> fp16
    attn_mma<<<dim3(NTILES / 2, NHEAD), 128, AT_SMEM>>>(qh, ql, vf, af);

    // 3) out = attn @ Wout + bias
    gemm_f16k<<<dim3(DIM / 128, SEQ / 64), 256, GF_SMEM>>>(
        af, wof, out, nullptr, SEQ, DIM, DIM, bias);
}

// round 17
// speedup vs baseline: 1.7338x; 1.0261x over previous
#include <cuda_runtime.h>
#include <cuda_bf16.h>
#include <cuda_fp16.h>
#include <cstdint>

#define SEQ 2048
#define DIM 1024
#define NHEAD 16
#define DHEAD 64
#define QKV_N (3 * DIM)   // 3072
#define QK_N (2 * DIM)    // 2048
#define NTILES (SEQ / 64) // 32

// ---------------------------------------------------------------------------
// Scratch (device globals — allocation-free rule)
// ---------------------------------------------------------------------------
__device__ __half g_x_hi[SEQ * DIM];      // fp16(x)
__device__ __half g_x_lo[SEQ * DIM];      // fp16 residual
__device__ __half g_wqk_f16[QK_N * DIM];  // [N,K] transposed, QK cols
__device__ __half g_wvt_f16[DIM * DIM];   // [N,K] transposed, V cols
__device__ __half g_qk_f16[SEQ * QK_N];   // Q,K fp16
__device__ __half g_v_f16[SEQ * DIM];     // V fp16
__device__ __half g_wout_f16[DIM * DIM];  // [N,K] transposed
__device__ __half g_attn_f16[SEQ * DIM];  // attention output

// ---------------------------------------------------------------------------
// PTX helpers
// ---------------------------------------------------------------------------
__device__ __forceinline__ uint32_t smem_u32(const void* p) {
    uint32_t a;
    asm("{ .reg .u64 t; cvta.to.shared.u64 t, %1; cvt.u32.u64 %0, t; }"
        : "=r"(a) : "l"(p));
    return a;
}

__device__ __forceinline__ void ldsm_x4(uint32_t* r, uint32_t addr) {
    asm volatile("ldmatrix.sync.aligned.m8n8.x4.shared.b16 {%0,%1,%2,%3}, [%4];"
                 : "=r"(r[0]), "=r"(r[1]), "=r"(r[2]), "=r"(r[3]) : "r"(addr));
}

__device__ __forceinline__ void ldsm_x4_t(uint32_t* r, uint32_t addr) {
    asm volatile("ldmatrix.sync.aligned.m8n8.x4.trans.shared.b16 {%0,%1,%2,%3}, [%4];"
                 : "=r"(r[0]), "=r"(r[1]), "=r"(r[2]), "=r"(r[3]) : "r"(addr));
}

// fp16 inputs, fp32 accumulator
__device__ __forceinline__ void mma_f16(float* d, const uint32_t* a,
                                        const uint32_t* b) {
    asm("mma.sync.aligned.m16n8k16.row.col.f32.f16.f16.f32 "
        "{%0,%1,%2,%3}, {%4,%5,%6,%7}, {%8,%9}, {%0,%1,%2,%3};"
        : "+f"(d[0]), "+f"(d[1]), "+f"(d[2]), "+f"(d[3])
        : "r"(a[0]), "r"(a[1]), "r"(a[2]), "r"(a[3]), "r"(b[0]), "r"(b[1]));
}

__device__ __forceinline__ void cp16(uint32_t dst, const void* src) {
    asm volatile("cp.async.cg.shared.global [%0], [%1], 16;"
                 :: "r"(dst), "l"(src));
}
#define CP_WAIT_ALL() asm volatile("cp.async.wait_all;" ::: "memory")

// swizzled smem byte offset for (row, 16B-seg), 128B rows (8 segs)
#define SWZ(r, seg) ((uint32_t)((r) * 128 + (((seg) ^ ((r) & 7)) << 4)))

__device__ __forceinline__ uint32_t pack_f16(float x, float y) {
    __half2 h = __floats2half2_rn(x, y);
    return *reinterpret_cast<uint32_t*>(&h);
}

// pack 2 floats into fp16 hi + fp16 residual lo
__device__ __forceinline__ void split_pack_f16(float x, float y,
                                               uint32_t& hi, uint32_t& lo) {
    __half2 h = __floats2half2_rn(x, y);
    float2 hf = __half22float2(h);
    __half2 l = __floats2half2_rn(x - hf.x, y - hf.y);
    hi = *reinterpret_cast<uint32_t*>(&h);
    lo = *reinterpret_cast<uint32_t*>(&l);
}

// ---------------------------------------------------------------------------
// Elementwise split: fp32 -> fp16 hi + fp16 lo
// ---------------------------------------------------------------------------
__global__ __launch_bounds__(256) void split_kernel(
    const float* __restrict__ in,
    __half* __restrict__ hi, __half* __restrict__ lo)
{
    int i = (blockIdx.x * 256 + threadIdx.x) * 4;
    float4 v = *(const float4*)(in + i);
    uint32_t h0, l0, h1, l1;
    split_pack_f16(v.x, v.y, h0, l0);
    split_pack_f16(v.z, v.w, h1, l1);
    *(uint32_t*)(hi + i)     = h0;
    *(uint32_t*)(hi + i + 2) = h1;
    *(uint32_t*)(lo + i)     = l0;
    *(uint32_t*)(lo + i + 2) = l1;
}

// ---------------------------------------------------------------------------
// Unified weight prep: transpose + fp16 convert for all three weight blocks.
// grid = (128, 32): bx<64 -> Wqkv QK cols; bx<96 -> Wqkv V cols; else Wout.
// ---------------------------------------------------------------------------
__global__ __launch_bounds__(256) void wprep_kernel(
    const float* __restrict__ Wqkv, const float* __restrict__ Wout,
    __half* __restrict__ wqk, __half* __restrict__ wvt,
    __half* __restrict__ wof)
{
    __shared__ float t[32][33];
    const int bx = blockIdx.x, k0 = blockIdx.y * 32;
    const int tx = threadIdx.x, ty = threadIdx.y;   // 32 x 8

    const float* src; int srcN, n0; __half* dst;
    if (bx < 64)      { src = Wqkv;        srcN = QKV_N; n0 = bx * 32;        dst = wqk; }
    else if (bx < 96) { src = Wqkv + QK_N; srcN = QKV_N; n0 = (bx - 64) * 32; dst = wvt; }
    else              { src = Wout;        srcN = DIM;   n0 = (bx - 96) * 32; dst = wof; }

    #pragma unroll
    for (int j = 0; j < 4; j++)
        t[ty + 8 * j][tx] = src[(size_t)(k0 + ty + 8 * j) * srcN + n0 + tx];
    __syncthreads();

    #pragma unroll
    for (int j = 0; j < 4; j++) {
        int row = ty + 8 * j;
        dst[(size_t)(n0 + row) * DIM + k0 + tx] = __float2half(t[tx][row]);
    }
}

// ---------------------------------------------------------------------------
// 2-term QK GEMM: Q,K = (xhi + xlo) @ Whi^T.  Output plain fp16.
// 64x128 CTA tile, BK=64, single 32KB buffer, 8 warps 2m x 4n (warp 32x32).
// ---------------------------------------------------------------------------
#define GQ_SMEM 32768

__global__ __launch_bounds__(256, 2) void gemm_qk(
    const __half* __restrict__ Ahi, const __half* __restrict__ Alo,
    const __half* __restrict__ Bh,
    __half* __restrict__ C16,
    int Mtot, int Ntot, int Ktot)
{
    extern __shared__ char smem[];
    const uint32_t sb = smem_u32(smem);
    const int tid  = threadIdx.x;
    const int wid  = tid >> 5;
    const int lane = tid & 31;
    const int row0 = blockIdx.y * 64, col0 = blockIdx.x * 128;

    const int m0 = (wid & 1) * 32;
    const int n0 = (wid >> 1) * 32;

    const uint32_t sAh = sb;            // 64x128B = 8K
    const uint32_t sAl = sb + 8192;
    const uint32_t sBh = sb + 16384;    // 128x128B = 16K

    float acc[2][4][4] = {};

    const int nchunks = Ktot >> 6;
    for (int c = 0; c < nchunks; c++) {
        #pragma unroll
        for (int i = 0; i < 8; i++) {
            int idx = tid + i * 256;
            if (i < 2) {
                int l = idx;                   // 0..511
                int r = l >> 3, sg = l & 7;
                cp16(sAh + SWZ(r, sg),
                     Ahi + (size_t)(row0 + r) * Ktot + c * 64 + sg * 8);
            } else if (i < 4) {
                int l = idx - 512;
                int r = l >> 3, sg = l & 7;
                cp16(sAl + SWZ(r, sg),
                     Alo + (size_t)(row0 + r) * Ktot + c * 64 + sg * 8);
            } else {
                int l = idx - 1024;            // 0..1023
                int r = l >> 3, sg = l & 7;
                cp16(sBh + SWZ(r, sg),
                     Bh + (size_t)(col0 + r) * Ktot + c * 64 + sg * 8);
            }
        }
        CP_WAIT_ALL();
        __syncthreads();

        #pragma unroll
        for (int ks = 0; ks < 4; ks++) {
            uint32_t aH[2][4], aL[2][4];
            #pragma unroll
            for (int mt = 0; mt < 2; mt++) {
                int r   = m0 + mt * 16 + (lane & 15);
                int seg = ks * 2 + (lane >> 4);
                uint32_t off = SWZ(r, seg);
                ldsm_x4(aH[mt], sAh + off);
                ldsm_x4(aL[mt], sAl + off);
            }
            #pragma unroll
            for (int np = 0; np < 2; np++) {
                int nr  = n0 + np * 16 + ((lane >> 4) << 3) + (lane & 7);
                int seg = ks * 2 + ((lane >> 3) & 1);
                uint32_t bH[4];
                ldsm_x4(bH, sBh + SWZ(nr, seg));
                #pragma unroll
                for (int mt = 0; mt < 2; mt++) {
                    mma_f16(acc[mt][np * 2],     aH[mt], bH);
                    mma_f16(acc[mt][np * 2 + 1], aH[mt], bH + 2);
                    mma_f16(acc[mt][np * 2],     aL[mt], bH);
                    mma_f16(acc[mt][np * 2 + 1], aL[mt], bH + 2);
                }
            }
        }
        __syncthreads();
    }

    #pragma unroll
    for (int mt = 0; mt < 2; mt++) {
        int r = row0 + m0 + mt * 16 + (lane >> 2);
        #pragma unroll
        for (int nt = 0; nt < 4; nt++) {
            int cc = col0 + n0 + nt * 8 + (lane & 3) * 2;
            *(uint32_t*)&C16[(size_t)r * Ntot + cc] =
                pack_f16(acc[mt][nt][0], acc[mt][nt][1]);
            *(uint32_t*)&C16[(size_t)(r + 8) * Ntot + cc] =
                pack_f16(acc[mt][nt][2], acc[mt][nt][3]);
        }
    }
}

// ---------------------------------------------------------------------------
// Single-term fp16 GEMM (V projection / out projection).
// 64x128 tile, BK=64, single 24KB buffer.
// ---------------------------------------------------------------------------
#define GF_SMEM 24576

__global__ __launch_bounds__(256, 2) void gemm_f16k(
    const __half* __restrict__ A, const __half* __restrict__ Bt,
    float* __restrict__ C, __half* __restrict__ C16,
    int Mtot, int Ntot, int Ktot,
    const float* __restrict__ bias)
{
    extern __shared__ char smem[];
    const uint32_t sb = smem_u32(smem);
    const int tid  = threadIdx.x;
    const int wid  = tid >> 5;
    const int lane = tid & 31;
    const int row0 = blockIdx.y * 64, col0 = blockIdx.x * 128;

    const int m0 = (wid & 1) * 32;
    const int n0 = (wid >> 1) * 32;

    const uint32_t sA = sb;
    const uint32_t sB = sb + 8192;

    float acc[2][4][4] = {};
    const int nchunks = Ktot >> 6;

    for (int c = 0; c < nchunks; c++) {
        #pragma unroll
        for (int i = 0; i < 6; i++) {
            if (i < 2) {
                int local = tid + i * 256;
                int r = local >> 3, seg = local & 7;
                cp16(sA + SWZ(r, seg),
                     A + (size_t)(row0 + r) * Ktot + c * 64 + seg * 8);
            } else {
                int local = tid + (i - 2) * 256;
                int r = local >> 3, seg = local & 7;
                cp16(sB + SWZ(r, seg),
                     Bt + (size_t)(col0 + r) * Ktot + c * 64 + seg * 8);
            }
        }
        CP_WAIT_ALL();
        __syncthreads();

        #pragma unroll
        for (int ks = 0; ks < 4; ks++) {
            uint32_t aH[2][4];
            #pragma unroll
            for (int mt = 0; mt < 2; mt++) {
                int r   = m0 + mt * 16 + (lane & 15);
                int seg = ks * 2 + (lane >> 4);
                ldsm_x4(aH[mt], sA + SWZ(r, seg));
            }
            #pragma unroll
            for (int np = 0; np < 2; np++) {
                int nr  = n0 + np * 16 + ((lane >> 4) << 3) + (lane & 7);
                int seg = ks * 2 + ((lane >> 3) & 1);
                uint32_t bH[4];
                ldsm_x4(bH, sB + SWZ(nr, seg));
                #pragma unroll
                for (int mt = 0; mt < 2; mt++) {
                    mma_f16(acc[mt][np * 2],     aH[mt], bH);
                    mma_f16(acc[mt][np * 2 + 1], aH[mt], bH + 2);
                }
            }
        }
        __syncthreads();
    }

    #pragma unroll
    for (int mt = 0; mt < 2; mt++) {
        int r = row0 + m0 + mt * 16 + (lane >> 2);
        #pragma unroll
        for (int nt = 0; nt < 4; nt++) {
            int cc = col0 + n0 + nt * 8 + (lane & 3) * 2;
            float bx = 0.f, by = 0.f;
            if (bias) { bx = bias[cc]; by = bias[cc + 1]; }
            float v0x = acc[mt][nt][0] + bx, v0y = acc[mt][nt][1] + by;
            float v1x = acc[mt][nt][2] + bx, v1y = acc[mt][nt][3] + by;
            if (C16) {
                *(uint32_t*)&C16[(size_t)r * Ntot + cc]       = pack_f16(v0x, v0y);
                *(uint32_t*)&C16[(size_t)(r + 8) * Ntot + cc] = pack_f16(v1x, v1y);
            } else {
                *(float2*)&C[(size_t)r * Ntot + cc]       = make_float2(v0x, v0y);
                *(float2*)&C[(size_t)(r + 8) * Ntot + cc] = make_float2(v1x, v1y);
            }
        }
    }
}

// ---------------------------------------------------------------------------
// Paired-tile flash attention. QK^T: single-term fp16, f32 accum.
// PV: single-term fp16, f32 accum. smem 32KB -> 4 CTAs/SM.
// ---------------------------------------------------------------------------
#define AT_SMEM 32768

__global__ __launch_bounds__(128, 4) void attn_mma(
    const __half* __restrict__ qk_f16,
    const __half* __restrict__ v_f16,
    __half* __restrict__ out_f16)
{
    extern __shared__ char smem[];
    const uint32_t sb = smem_u32(smem);
    const uint32_t sQ1 = sb;
    const uint32_t sQ2 = sb + 8192;
    const uint32_t sK  = sb + 16384;
    const uint32_t sV  = sb + 24576;

    const int tid = threadIdx.x, wid = tid >> 5, lane = tid & 31;
    const int t1 = blockIdx.x;
    const int t2 = (NTILES - 1) - t1;
    const int h  = blockIdx.y;
    const int hoff = h * DHEAD;

    #pragma unroll
    for (int i = 0; i < 4; i++) {
        int idx = tid + i * 128;
        int r = idx >> 3, seg = idx & 7;
        uint32_t off = SWZ(r, seg);
        cp16(sQ1 + off, qk_f16 + (size_t)(t1 * 64 + r) * QK_N + hoff + seg * 8);
        cp16(sQ2 + off, qk_f16 + (size_t)(t2 * 64 + r) * QK_N + hoff + seg * 8);
    }

    float o1[8][4] = {}, o2[8][4] = {};
    float m1[2] = {-1e30f, -1e30f}, l1[2] = {0.f, 0.f};
    float m2[2] = {-1e30f, -1e30f}, l2[2] = {0.f, 0.f};

    const int rloc = wid * 16 + (lane >> 2);
    const int rA1 = t1 * 64 + rloc;
    const int rA2 = t2 * 64 + rloc;

    auto process = [&](uint32_t sQ, float (*o)[4],
                       float* m_i, float* l_i, int rA, bool maskit, int k0) {
        // S = Q K^T (single-term fp16, f32 accum)
        float s[8][4] = {};
        #pragma unroll
        for (int ks = 0; ks < 4; ks++) {
            uint32_t aH[4];
            {
                int r   = wid * 16 + (lane & 15);
                int seg = ks * 2 + (lane >> 4);
                ldsm_x4(aH, sQ + SWZ(r, seg));
            }
            #pragma unroll
            for (int np = 0; np < 4; np++) {
                int nr = np * 16 + ((lane >> 4) << 3) + (lane & 7);
                int sg = ks * 2 + ((lane >> 3) & 1);
                uint32_t bH[4];
                ldsm_x4(bH, sK + SWZ(nr, sg));
                mma_f16(s[np * 2],     aH, bH);
                mma_f16(s[np * 2 + 1], aH, bH + 2);
            }
        }

        // scale + causal mask
        #pragma unroll
        for (int j = 0; j < 8; j++) {
            s[j][0] *= 0.125f; s[j][1] *= 0.125f;
            s[j][2] *= 0.125f; s[j][3] *= 0.125f;
        }
        if (maskit) {
            #pragma unroll
            for (int j = 0; j < 8; j++) {
                int col = k0 + j * 8 + (lane & 3) * 2;
                if (col > rA)         s[j][0] = -1e30f;
                if (col + 1 > rA)     s[j][1] = -1e30f;
                if (col > rA + 8)     s[j][2] = -1e30f;
                if (col + 1 > rA + 8) s[j][3] = -1e30f;
            }
        }

        // online softmax on fragments
        float mxA = -1e30f, mxB = -1e30f;
        #pragma unroll
        for (int j = 0; j < 8; j++) {
            mxA = fmaxf(mxA, fmaxf(s[j][0], s[j][1]));
            mxB = fmaxf(mxB, fmaxf(s[j][2], s[j][3]));
        }
        mxA = fmaxf(mxA, __shfl_xor_sync(0xffffffffu, mxA, 1));
        mxA = fmaxf(mxA, __shfl_xor_sync(0xffffffffu, mxA, 2));
        mxB = fmaxf(mxB, __shfl_xor_sync(0xffffffffu, mxB, 1));
        mxB = fmaxf(mxB, __shfl_xor_sync(0xffffffffu, mxB, 2));

        float mA = fmaxf(m_i[0], mxA), mB = fmaxf(m_i[1], mxB);
        float scA = __expf(m_i[0] - mA), scB = __expf(m_i[1] - mB);
        float lA = 0.f, lB = 0.f;
        #pragma unroll
        for (int j = 0; j < 8; j++) {
            s[j][0] = __expf(s[j][0] - mA);
            s[j][1] = __expf(s[j][1] - mA);
            s[j][2] = __expf(s[j][2] - mB);
            s[j][3] = __expf(s[j][3] - mB);
            lA += s[j][0] + s[j][1];
            lB += s[j][2] + s[j][3];
        }
        lA += __shfl_xor_sync(0xffffffffu, lA, 1);
        lA += __shfl_xor_sync(0xffffffffu, lA, 2);
        lB += __shfl_xor_sync(0xffffffffu, lB, 1);
        lB += __shfl_xor_sync(0xffffffffu, lB, 2);
        l_i[0] = l_i[0] * scA + lA;  m_i[0] = mA;
        l_i[1] = l_i[1] * scB + lB;  m_i[1] = mB;
        #pragma unroll
        for (int j = 0; j < 8; j++) {
            o[j][0] *= scA; o[j][1] *= scA;
            o[j][2] *= scB; o[j][3] *= scB;
        }

        // O += P V  (single-term fp16, f32 accum)
        #pragma unroll
        for (int t = 0; t < 4; t++) {
            uint32_t pH[4];
            pH[0] = pack_f16(s[2 * t][0],     s[2 * t][1]);
            pH[1] = pack_f16(s[2 * t][2],     s[2 * t][3]);
            pH[2] = pack_f16(s[2 * t + 1][0], s[2 * t + 1][1]);
            pH[3] = pack_f16(s[2 * t + 1][2], s[2 * t + 1][3]);
            #pragma unroll
            for (int sp = 0; sp < 4; sp++) {
                int g  = lane >> 3, rr = lane & 7;
                uint32_t off = SWZ(t * 16 + rr + ((g & 1) << 3),
                                   sp * 2 + (g >> 1));
                uint32_t bH[4];
                ldsm_x4_t(bH, sV + off);
                mma_f16(o[sp * 2],     pH, bH);
                mma_f16(o[sp * 2 + 1], pH, bH + 2);
            }
        }
    };

    for (int kt = 0; kt <= t2; kt++) {
        const int k0 = kt * 64;

        #pragma unroll
        for (int i = 0; i < 4; i++) {
            int idx = tid + i * 128;
            int r = idx >> 3, seg = idx & 7;
            uint32_t off = SWZ(r, seg);
            cp16(sK + off,
                 qk_f16 + (size_t)(k0 + r) * QK_N + DIM + hoff + seg * 8);
            cp16(sV + off,
                 v_f16 + (size_t)(k0 + r) * DIM + hoff + seg * 8);
        }
        CP_WAIT_ALL();
        __syncthreads();

        process(sQ2, o2, m2, l2, rA2, kt == t2, k0);
        if (kt <= t1)
            process(sQ1, o1, m1, l1, rA1, kt == t1, k0);

        __syncthreads();
    }

    // epilogue: normalize, write fp16
    {
        float invA = 1.0f / l2[0], invB = 1.0f / l2[1];
        #pragma unroll
        for (int j = 0; j < 8; j++) {
            int d = hoff + j * 8 + (lane & 3) * 2;
            *(uint32_t*)&out_f16[(size_t)rA2 * DIM + d] =
                pack_f16(o2[j][0] * invA, o2[j][1] * invA);
            *(uint32_t*)&out_f16[(size_t)(rA2 + 8) * DIM + d] =
                pack_f16(o2[j][2] * invB, o2[j][3] * invB);
        }
    }
    {
        float invA = 1.0f / l1[0], invB = 1.0f / l1[1];
        #pragma unroll
        for (int j = 0; j < 8; j++) {
            int d = hoff + j * 8 + (lane & 3) * 2;
            *(uint32_t*)&out_f16[(size_t)rA1 * DIM + d] =
                pack_f16(o1[j][0] * invA, o1[j][1] * invA);
            *(uint32_t*)&out_f16[(size_t)(rA1 + 8) * DIM + d] =
                pack_f16(o1[j][2] * invB, o1[j][3] * invB);
        }
    }
}

// ---------------------------------------------------------------------------
extern "C" void kernel_launch(void* const* d_in, const int* in_sizes, int n_in,
                              void* d_out, int out_size)
{
    const float* x    = (const float*)d_in[0];
    const float* Wqkv = (const float*)d_in[1];
    const float* Wout = (const float*)d_in[2];
    const float* bias = (const float*)d_in[3];
    float* out = (float*)d_out;

    __half *xh, *xl, *wqk, *wvt, *qk, *vf, *wof, *af;
    cudaGetSymbolAddress((void**)&xh,  g_x_hi);
    cudaGetSymbolAddress((void**)&xl,  g_x_lo);
    cudaGetSymbolAddress((void**)&wqk, g_wqk_f16);
    cudaGetSymbolAddress((void**)&wvt, g_wvt_f16);
    cudaGetSymbolAddress((void**)&qk,  g_qk_f16);
    cudaGetSymbolAddress((void**)&vf,  g_v_f16);
    cudaGetSymbolAddress((void**)&wof, g_wout_f16);
    cudaGetSymbolAddress((void**)&af,  g_attn_f16);

    cudaFuncSetAttribute(gemm_qk, cudaFuncAttributeMaxDynamicSharedMemorySize,
                         GQ_SMEM);
    cudaFuncSetAttribute(gemm_f16k, cudaFuncAttributeMaxDynamicSharedMemorySize,
                         GF_SMEM);
    cudaFuncSetAttribute(attn_mma, cudaFuncAttributeMaxDynamicSharedMemorySize,
                         AT_SMEM);

    // Prep: split x + unified weight transpose/convert
    split_kernel<<<SEQ * DIM / 1024, 256>>>(x, xh, xl);
    wprep_kernel<<<dim3(128, 32), dim3(32, 8)>>>(Wqkv, Wout, wqk, wvt, wof);

    // 1a) Q,K = (xhi + xlo) @ Wqk^T  (2-term, plain fp16 out)
    gemm_qk<<<dim3(QK_N / 128, SEQ / 64), 256, GQ_SMEM>>>(
        xh, xl, wqk, qk, SEQ, QK_N, DIM);

    // 1b) V = xhi @ Wv^T  (single fp16)
    gemm_f16k<<<dim3(DIM / 128, SEQ / 64), 256, GF_SMEM>>>(
        xh, wvt, nullptr, vf, SEQ, DIM, DIM, nullptr);

    // 2) attention (paired tiles, single-term fp16) -> fp16
    attn_mma<<<dim3(NTILES / 2, NHEAD), 128, AT_SMEM>>>(qk, vf, af);

    // 3) out = attn @ Wout + bias
    gemm_f16k<<<dim3(DIM / 128, SEQ / 64), 256, GF_SMEM>>>(
        af, wof, out, nullptr, SEQ, DIM, DIM, bias);
}